// round 2
// baseline (speedup 1.0000x reference)
#include <cuda_runtime.h>
#include <math.h>

// ---------------------------------------------------------------------------
// Scratch (device globals — no runtime allocation allowed)
// Layouts: [b][c][s] with s = h*w = 4096 contiguous; scores [b][i][j].
// ---------------------------------------------------------------------------
#define B4 4
#define C512 512
#define HW 4096
#define NG 32

__device__ float g_h[(size_t)B4 * C512 * HW];                 // 32 MB groupnorm out
__device__ float g_q[(size_t)B4 * C512 * HW];
__device__ float g_k[(size_t)B4 * C512 * HW];
__device__ float g_v[(size_t)B4 * C512 * HW];
__device__ float g_o[(size_t)B4 * C512 * HW];
__device__ float g_s[(size_t)B4 * HW * HW];                   // 256 MB scores/attn

// ---------------------------------------------------------------------------
// GroupNorm: one block per (b, g). Group = 16 channels x 4096 spatial,
// contiguous 65536 floats.
// ---------------------------------------------------------------------------
__global__ __launch_bounds__(256) void groupnorm_kernel(
    const float* __restrict__ x, const float* __restrict__ gamma,
    const float* __restrict__ beta, float* __restrict__ out)
{
    const int GSZ = (C512 / NG) * HW;  // 65536
    int b = blockIdx.x >> 5;
    int g = blockIdx.x & 31;
    const float* xp = x + ((size_t)b * C512 + g * (C512 / NG)) * HW;
    float* op = out + ((size_t)b * C512 + g * (C512 / NG)) * HW;

    float s = 0.f, sq = 0.f;
    for (int i = threadIdx.x * 4; i < GSZ; i += blockDim.x * 4) {
        float4 v = *(const float4*)(xp + i);
        s  += v.x + v.y + v.z + v.w;
        sq += v.x * v.x + v.y * v.y + v.z * v.z + v.w * v.w;
    }
    __shared__ float red0[8], red1[8];
    #pragma unroll
    for (int o = 16; o > 0; o >>= 1) {
        s  += __shfl_xor_sync(0xffffffffu, s, o);
        sq += __shfl_xor_sync(0xffffffffu, sq, o);
    }
    if ((threadIdx.x & 31) == 0) { red0[threadIdx.x >> 5] = s; red1[threadIdx.x >> 5] = sq; }
    __syncthreads();
    s = 0.f; sq = 0.f;
    #pragma unroll
    for (int i = 0; i < 8; i++) { s += red0[i]; sq += red1[i]; }
    float mean = s / GSZ;
    float var  = sq / GSZ - mean * mean;
    float rstd = rsqrtf(var + 1e-6f);

    for (int i = threadIdx.x * 4; i < GSZ; i += blockDim.x * 4) {
        int c = g * (C512 / NG) + (i >> 12);
        float w  = gamma[c] * rstd;
        float bb = beta[c] - mean * w;
        float4 v = *(const float4*)(xp + i);
        v.x = v.x * w + bb; v.y = v.y * w + bb; v.z = v.z * w + bb; v.w = v.w * w + bb;
        *(float4*)(op + i) = v;
    }
}

// ---------------------------------------------------------------------------
// Tiled SGEMM: C[m][n] = alpha * sum_k A(m,k)*B(k,n) + bias[m] + resid[m][n]
// TA=0: A is MxK row-major (lda=K). TA=1: A stored KxM (lda=M).
// TB=0: B is KxN row-major (ldb=N). TB=1: B stored NxK (ldb=K).
// BM=BN=128, BK=8, 256 threads, 8x8 per thread (split 4+4 at +64),
// double-buffered smem. Requires M,N % 128 == 0 and K % 8 == 0.
// ---------------------------------------------------------------------------
#define BM 128
#define BN 128
#define BK 8

template <int TA, int TB>
__global__ __launch_bounds__(256, 2) void sgemm_kernel(
    int M, int N, int K,
    const float* __restrict__ A, long long sA,
    const float* __restrict__ B, long long sB,
    float* __restrict__ C, long long sC,
    const float* __restrict__ bias,
    const float* __restrict__ resid, long long sR,
    float alpha)
{
    __shared__ float As[2][BK][BM + 4];
    __shared__ float Bs[2][BK][BN + 4];

    const int tid = threadIdx.x;
    const int bm0 = blockIdx.y * BM;
    const int bn0 = blockIdx.x * BN;
    const int bz = blockIdx.z;

    A += (size_t)bz * sA;
    B += (size_t)bz * sB;
    C += (size_t)bz * sC;
    if (resid) resid += (size_t)bz * sR;

    const int lda = TA ? M : K;
    const int ldb = TB ? K : N;

    // per-thread gmem load coordinates (one float4 each per tile)
    const int a_r = TA ? (tid >> 5) : (tid >> 1);            // TA: k row, else m row
    const int a_c = TA ? ((tid & 31) << 2) : ((tid & 1) << 2);
    const float* Aptr = TA ? (A + (size_t)a_r * lda + bm0 + a_c)
                           : (A + (size_t)(bm0 + a_r) * lda + a_c);
    const long long a_step = TA ? (long long)BK * lda : (long long)BK;

    const int b_r = TB ? (tid >> 1) : (tid >> 5);            // TB: n row, else k row
    const int b_c = TB ? ((tid & 1) << 2) : ((tid & 31) << 2);
    const float* Bptr = TB ? (B + (size_t)(bn0 + b_r) * ldb + b_c)
                           : (B + (size_t)b_r * ldb + bn0 + b_c);
    const long long b_step = TB ? (long long)BK : (long long)BK * ldb;

    float4 aload = *(const float4*)Aptr;
    float4 bload = *(const float4*)Bptr;

    // stage tile 0 into buffer 0
    if (TA) {
        *(float4*)&As[0][a_r][a_c] = aload;
    } else {
        As[0][a_c + 0][a_r] = aload.x;
        As[0][a_c + 1][a_r] = aload.y;
        As[0][a_c + 2][a_r] = aload.z;
        As[0][a_c + 3][a_r] = aload.w;
    }
    if (TB) {
        Bs[0][b_c + 0][b_r] = bload.x;
        Bs[0][b_c + 1][b_r] = bload.y;
        Bs[0][b_c + 2][b_r] = bload.z;
        Bs[0][b_c + 3][b_r] = bload.w;
    } else {
        *(float4*)&Bs[0][b_r][b_c] = bload;
    }
    __syncthreads();

    const int tm = (tid >> 4) << 2;   // 0..60
    const int tn = (tid & 15) << 2;   // 0..60

    float acc[8][8] = {};
    const int nk = K / BK;
    int buf = 0;

    for (int kt = 0; kt < nk; kt++) {
        const bool pref = (kt + 1 < nk);
        if (pref) {
            aload = *(const float4*)(Aptr + (size_t)(kt + 1) * a_step);
            bload = *(const float4*)(Bptr + (size_t)(kt + 1) * b_step);
        }
        #pragma unroll
        for (int kk = 0; kk < BK; kk++) {
            float a[8], b[8];
            *(float4*)&a[0] = *(const float4*)&As[buf][kk][tm];
            *(float4*)&a[4] = *(const float4*)&As[buf][kk][tm + 64];
            *(float4*)&b[0] = *(const float4*)&Bs[buf][kk][tn];
            *(float4*)&b[4] = *(const float4*)&Bs[buf][kk][tn + 64];
            #pragma unroll
            for (int i = 0; i < 8; i++)
                #pragma unroll
                for (int j = 0; j < 8; j++)
                    acc[i][j] += a[i] * b[j];
        }
        if (pref) {
            const int nb = buf ^ 1;
            if (TA) {
                *(float4*)&As[nb][a_r][a_c] = aload;
            } else {
                As[nb][a_c + 0][a_r] = aload.x;
                As[nb][a_c + 1][a_r] = aload.y;
                As[nb][a_c + 2][a_r] = aload.z;
                As[nb][a_c + 3][a_r] = aload.w;
            }
            if (TB) {
                Bs[nb][b_c + 0][b_r] = bload.x;
                Bs[nb][b_c + 1][b_r] = bload.y;
                Bs[nb][b_c + 2][b_r] = bload.z;
                Bs[nb][b_c + 3][b_r] = bload.w;
            } else {
                *(float4*)&Bs[nb][b_r][b_c] = bload;
            }
        }
        __syncthreads();
        buf ^= 1;
    }

    // epilogue
    #pragma unroll
    for (int i = 0; i < 8; i++) {
        const int m = bm0 + tm + ((i < 4) ? i : (60 + i));
        const float bval = bias ? bias[m] : 0.f;
        float* crow = C + (size_t)m * N + bn0;
        float4 v0, v1;
        v0.x = acc[i][0] * alpha + bval;
        v0.y = acc[i][1] * alpha + bval;
        v0.z = acc[i][2] * alpha + bval;
        v0.w = acc[i][3] * alpha + bval;
        v1.x = acc[i][4] * alpha + bval;
        v1.y = acc[i][5] * alpha + bval;
        v1.z = acc[i][6] * alpha + bval;
        v1.w = acc[i][7] * alpha + bval;
        if (resid) {
            const float* rrow = resid + (size_t)m * N + bn0;
            float4 r0 = *(const float4*)(rrow + tn);
            float4 r1 = *(const float4*)(rrow + tn + 64);
            v0.x += r0.x; v0.y += r0.y; v0.z += r0.z; v0.w += r0.w;
            v1.x += r1.x; v1.y += r1.y; v1.z += r1.z; v1.w += r1.w;
        }
        *(float4*)(crow + tn) = v0;
        *(float4*)(crow + tn + 64) = v1;
    }
}

// ---------------------------------------------------------------------------
// Row softmax over 4096 columns, in place. One block (256 thr) per row.
// ---------------------------------------------------------------------------
__global__ __launch_bounds__(256) void softmax_kernel(float* __restrict__ s)
{
    float* p = s + (size_t)blockIdx.x * HW;
    const int tid = threadIdx.x;

    float4 v[4];
    #pragma unroll
    for (int i = 0; i < 4; i++) v[i] = *(const float4*)(p + i * 1024 + tid * 4);

    float m = -1e30f;
    #pragma unroll
    for (int i = 0; i < 4; i++)
        m = fmaxf(m, fmaxf(fmaxf(v[i].x, v[i].y), fmaxf(v[i].z, v[i].w)));

    __shared__ float red[8];
    #pragma unroll
    for (int o = 16; o > 0; o >>= 1) m = fmaxf(m, __shfl_xor_sync(0xffffffffu, m, o));
    if ((tid & 31) == 0) red[tid >> 5] = m;
    __syncthreads();
    m = red[0];
    #pragma unroll
    for (int i = 1; i < 8; i++) m = fmaxf(m, red[i]);
    __syncthreads();

    float sum = 0.f;
    #pragma unroll
    for (int i = 0; i < 4; i++) {
        v[i].x = __expf(v[i].x - m);
        v[i].y = __expf(v[i].y - m);
        v[i].z = __expf(v[i].z - m);
        v[i].w = __expf(v[i].w - m);
        sum += v[i].x + v[i].y + v[i].z + v[i].w;
    }
    #pragma unroll
    for (int o = 16; o > 0; o >>= 1) sum += __shfl_xor_sync(0xffffffffu, sum, o);
    if ((tid & 31) == 0) red[tid >> 5] = sum;
    __syncthreads();
    sum = 0.f;
    #pragma unroll
    for (int i = 0; i < 8; i++) sum += red[i];

    const float inv = 1.f / sum;
    #pragma unroll
    for (int i = 0; i < 4; i++) {
        v[i].x *= inv; v[i].y *= inv; v[i].z *= inv; v[i].w *= inv;
        *(float4*)(p + i * 1024 + tid * 4) = v[i];
    }
}

// ---------------------------------------------------------------------------
// Launcher
// ---------------------------------------------------------------------------
extern "C" void kernel_launch(void* const* d_in, const int* in_sizes, int n_in,
                              void* d_out, int out_size)
{
    (void)in_sizes; (void)n_in; (void)out_size;
    const float* x    = (const float*)d_in[0];
    const float* gn_w = (const float*)d_in[1];
    const float* gn_b = (const float*)d_in[2];
    const float* wq   = (const float*)d_in[3];
    const float* bq   = (const float*)d_in[4];
    const float* wk   = (const float*)d_in[5];
    const float* bk   = (const float*)d_in[6];
    const float* wv   = (const float*)d_in[7];
    const float* bv   = (const float*)d_in[8];
    const float* wo   = (const float*)d_in[9];
    const float* bo   = (const float*)d_in[10];
    float* out = (float*)d_out;

    float *h_, *q, *k, *v, *o, *s;
    cudaGetSymbolAddress((void**)&h_, g_h);
    cudaGetSymbolAddress((void**)&q,  g_q);
    cudaGetSymbolAddress((void**)&k,  g_k);
    cudaGetSymbolAddress((void**)&v,  g_v);
    cudaGetSymbolAddress((void**)&o,  g_o);
    cudaGetSymbolAddress((void**)&s,  g_s);

    const long long SC = (long long)C512 * HW;   // per-batch stride for [c][s]
    const long long SS = (long long)HW * HW;     // per-batch stride for scores
    const float scale = 0.044194173824159216f;   // 512^-0.5

    groupnorm_kernel<<<B4 * NG, 256>>>(x, gn_w, gn_b, h_);

    dim3 gQKV(HW / BN, C512 / BM, B4);           // (32, 4, 4)
    sgemm_kernel<0, 0><<<gQKV, 256>>>(C512, HW, C512, wq, 0, h_, SC, q, SC, bq, nullptr, 0, 1.f);
    sgemm_kernel<0, 0><<<gQKV, 256>>>(C512, HW, C512, wk, 0, h_, SC, k, SC, bk, nullptr, 0, 1.f);
    sgemm_kernel<0, 0><<<gQKV, 256>>>(C512, HW, C512, wv, 0, h_, SC, v, SC, bv, nullptr, 0, 1.f);

    dim3 gS(HW / BN, HW / BM, B4);               // (32, 32, 4)
    sgemm_kernel<1, 0><<<gS, 256>>>(HW, HW, C512, q, SC, k, SC, s, SS, nullptr, nullptr, 0, scale);

    softmax_kernel<<<B4 * HW, 256>>>(s);

    sgemm_kernel<0, 1><<<gQKV, 256>>>(C512, HW, HW, v, SC, s, SS, o, SC, nullptr, nullptr, 0, 1.f);

    sgemm_kernel<0, 0><<<gQKV, 256>>>(C512, HW, C512, wo, 0, o, SC, out, SC, bo, x, SC, 1.f);
}

// round 3
// speedup vs baseline: 2.2189x; 2.2189x over previous
#include <cuda_runtime.h>
#include <math.h>
#include <stdint.h>

// ---------------------------------------------------------------------------
// Problem constants
// ---------------------------------------------------------------------------
#define B4 4
#define C512 512
#define HW 4096
#define NG 32

// Scratch (device globals — no runtime allocation allowed)
__device__ float g_h[(size_t)B4 * C512 * HW];
__device__ float g_q[(size_t)B4 * C512 * HW];
__device__ float g_k[(size_t)B4 * C512 * HW];
__device__ float g_v[(size_t)B4 * C512 * HW];
__device__ float g_o[(size_t)B4 * C512 * HW];
__device__ float g_s[(size_t)B4 * HW * HW];     // 256 MB scores/attn

// ---------------------------------------------------------------------------
// GroupNorm (unchanged from R1 — negligible time)
// ---------------------------------------------------------------------------
__global__ __launch_bounds__(256) void groupnorm_kernel(
    const float* __restrict__ x, const float* __restrict__ gamma,
    const float* __restrict__ beta, float* __restrict__ out)
{
    const int GSZ = (C512 / NG) * HW;  // 65536
    int b = blockIdx.x >> 5;
    int g = blockIdx.x & 31;
    const float* xp = x + ((size_t)b * C512 + g * (C512 / NG)) * HW;
    float* op = out + ((size_t)b * C512 + g * (C512 / NG)) * HW;

    float s = 0.f, sq = 0.f;
    for (int i = threadIdx.x * 4; i < GSZ; i += blockDim.x * 4) {
        float4 v = *(const float4*)(xp + i);
        s  += v.x + v.y + v.z + v.w;
        sq += v.x * v.x + v.y * v.y + v.z * v.z + v.w * v.w;
    }
    __shared__ float red0[8], red1[8];
    #pragma unroll
    for (int o = 16; o > 0; o >>= 1) {
        s  += __shfl_xor_sync(0xffffffffu, s, o);
        sq += __shfl_xor_sync(0xffffffffu, sq, o);
    }
    if ((threadIdx.x & 31) == 0) { red0[threadIdx.x >> 5] = s; red1[threadIdx.x >> 5] = sq; }
    __syncthreads();
    s = 0.f; sq = 0.f;
    #pragma unroll
    for (int i = 0; i < 8; i++) { s += red0[i]; sq += red1[i]; }
    float mean = s / GSZ;
    float var  = sq / GSZ - mean * mean;
    float rstd = rsqrtf(var + 1e-6f);

    for (int i = threadIdx.x * 4; i < GSZ; i += blockDim.x * 4) {
        int c = g * (C512 / NG) + (i >> 12);
        float w  = gamma[c] * rstd;
        float bb = beta[c] - mean * w;
        float4 v = *(const float4*)(xp + i);
        v.x = v.x * w + bb; v.y = v.y * w + bb; v.z = v.z * w + bb; v.w = v.w * w + bb;
        *(float4*)(op + i) = v;
    }
}

// ---------------------------------------------------------------------------
// tf32 tensor-core GEMM.
// C[m][n] = alpha * sum_k A(m,k)*B(k,n) + bias[m] + resid[m][n]
// TA=0: A row-major MxK (lda=K). TA=1: A stored KxM (lda=M).
// TB=0: B row-major KxN (ldb=N). TB=1: B stored NxK (ldb=K).
// Tiles: BM=BN=128, BK=32. 256 threads, warp grid 4(m) x 2(n), warp tile 32x64.
// mma.sync.m16n8k8.tf32, fp32 accumulate. Inputs cvt.rna to tf32 at smem store.
// smem: operand-major [128][32] per buffer, XOR swizzle:
//   idx(r,k) = r*32 + (k ^ ((r&7)<<2))   -> conflict-free STS.128 + frag LDS.
// Requires M,N % 128 == 0, K % 32 == 0.
// ---------------------------------------------------------------------------
__device__ __forceinline__ uint32_t f2tf(float f) {
    uint32_t r;
    asm("cvt.rna.tf32.f32 %0, %1;" : "=r"(r) : "f"(f));
    return r;
}

__device__ __forceinline__ void mma_tf32(float* c, const uint32_t* a, const uint32_t* b) {
    asm volatile(
        "mma.sync.aligned.m16n8k8.row.col.f32.tf32.tf32.f32 "
        "{%0,%1,%2,%3}, {%4,%5,%6,%7}, {%8,%9}, {%0,%1,%2,%3};"
        : "+f"(c[0]), "+f"(c[1]), "+f"(c[2]), "+f"(c[3])
        : "r"(a[0]), "r"(a[1]), "r"(a[2]), "r"(a[3]), "r"(b[0]), "r"(b[1]));
}

template <int TA, int TB>
__global__ __launch_bounds__(256) void mmagemm(
    int M, int N, int K,
    const float* __restrict__ A, long long sA,
    const float* __restrict__ B, long long sB,
    float* __restrict__ C, long long sC,
    const float* __restrict__ bias,
    const float* __restrict__ resid, long long sR,
    float alpha)
{
    extern __shared__ uint32_t sm[];
    uint32_t* As = sm;              // [2][128*32]
    uint32_t* Bs = sm + 2 * 4096;   // [2][128*32]

    const int tid = threadIdx.x;
    const int bm0 = blockIdx.y * 128;
    const int bn0 = blockIdx.x * 128;

    A += (size_t)blockIdx.z * sA;
    B += (size_t)blockIdx.z * sB;
    C += (size_t)blockIdx.z * sC;
    if (resid) resid += (size_t)blockIdx.z * sR;

    const int lda = TA ? M : K;
    const int ldb = TB ? K : N;

    const int lane = tid & 31;
    const int lr = lane >> 2;       // 0..7
    const int lc = lane & 3;        // 0..3
    const int wid = tid >> 5;
    const int wm0 = (wid & 3) * 32;
    const int wn0 = (wid >> 2) * 64;
    const int sxa = lr << 2;        // frag-load swizzle (row&7 == lr for all frag rows)

    // per-thread gmem base pointers
    const float* Ag;
    const float* Bg;
    if (TA == 0) Ag = A + (size_t)(bm0 + (tid >> 3)) * lda + (tid & 7) * 4;
    else         Ag = A + (size_t)((tid >> 7) * 16) * lda + bm0 + (tid & 127);
    if (TB == 1) Bg = B + (size_t)(bn0 + (tid >> 3)) * ldb + (tid & 7) * 4;
    else         Bg = B + (size_t)((tid >> 7) * 16) * ldb + bn0 + (tid & 127);

    float ar[16], br[16];
    float acc[2][8][4] = {};

    auto loadA = [&](int kt) {
        if (TA == 0) {
            #pragma unroll
            for (int p = 0; p < 4; p++)
                *(float4*)&ar[p * 4] =
                    *(const float4*)(Ag + (size_t)p * 32 * lda + (size_t)kt * 32);
        } else {
            #pragma unroll
            for (int u = 0; u < 16; u++)
                ar[u] = Ag[(size_t)(kt * 32 + u) * lda];
        }
    };
    auto loadB = [&](int kt) {
        if (TB == 1) {
            #pragma unroll
            for (int p = 0; p < 4; p++)
                *(float4*)&br[p * 4] =
                    *(const float4*)(Bg + (size_t)p * 32 * ldb + (size_t)kt * 32);
        } else {
            #pragma unroll
            for (int u = 0; u < 16; u++)
                br[u] = Bg[(size_t)(kt * 32 + u) * ldb];
        }
    };
    auto storeA = [&](int buf) {
        uint32_t* dst = As + buf * 4096;
        if (TA == 0) {
            const int m = tid >> 3, k4 = (tid & 7) * 4, sx = (m & 7) << 2;
            #pragma unroll
            for (int p = 0; p < 4; p++) {
                uint4 v = make_uint4(f2tf(ar[p * 4 + 0]), f2tf(ar[p * 4 + 1]),
                                     f2tf(ar[p * 4 + 2]), f2tf(ar[p * 4 + 3]));
                *(uint4*)&dst[(m + p * 32) * 32 + (k4 ^ sx)] = v;
            }
        } else {
            const int m = tid & 127, sx = (m & 7) << 2, kg = (tid >> 7) * 16;
            #pragma unroll
            for (int p = 0; p < 4; p++) {
                uint4 v = make_uint4(f2tf(ar[p * 4 + 0]), f2tf(ar[p * 4 + 1]),
                                     f2tf(ar[p * 4 + 2]), f2tf(ar[p * 4 + 3]));
                *(uint4*)&dst[m * 32 + ((kg + p * 4) ^ sx)] = v;
            }
        }
    };
    auto storeB = [&](int buf) {
        uint32_t* dst = Bs + buf * 4096;
        if (TB == 1) {
            const int n = tid >> 3, k4 = (tid & 7) * 4, sx = (n & 7) << 2;
            #pragma unroll
            for (int p = 0; p < 4; p++) {
                uint4 v = make_uint4(f2tf(br[p * 4 + 0]), f2tf(br[p * 4 + 1]),
                                     f2tf(br[p * 4 + 2]), f2tf(br[p * 4 + 3]));
                *(uint4*)&dst[(n + p * 32) * 32 + (k4 ^ sx)] = v;
            }
        } else {
            const int n = tid & 127, sx = (n & 7) << 2, kg = (tid >> 7) * 16;
            #pragma unroll
            for (int p = 0; p < 4; p++) {
                uint4 v = make_uint4(f2tf(br[p * 4 + 0]), f2tf(br[p * 4 + 1]),
                                     f2tf(br[p * 4 + 2]), f2tf(br[p * 4 + 3]));
                *(uint4*)&dst[n * 32 + ((kg + p * 4) ^ sx)] = v;
            }
        }
    };
    auto compute = [&](int buf) {
        const uint32_t* Ab = As + buf * 4096;
        const uint32_t* Bb = Bs + buf * 4096;
        #pragma unroll
        for (int ks = 0; ks < 4; ks++) {
            const int kb = ks * 8;
            const int o0 = (kb + lc) ^ sxa;
            const int o1 = (kb + lc + 4) ^ sxa;
            uint32_t af[2][4], bf[8][2];
            #pragma unroll
            for (int i = 0; i < 2; i++) {
                const int m0 = wm0 + i * 16 + lr;
                af[i][0] = Ab[m0 * 32 + o0];
                af[i][1] = Ab[(m0 + 8) * 32 + o0];
                af[i][2] = Ab[m0 * 32 + o1];
                af[i][3] = Ab[(m0 + 8) * 32 + o1];
            }
            #pragma unroll
            for (int j = 0; j < 8; j++) {
                const int n0 = wn0 + j * 8 + lr;
                bf[j][0] = Bb[n0 * 32 + o0];
                bf[j][1] = Bb[n0 * 32 + o1];
            }
            #pragma unroll
            for (int i = 0; i < 2; i++)
                #pragma unroll
                for (int j = 0; j < 8; j++)
                    mma_tf32(acc[i][j], af[i], bf[j]);
        }
    };

    const int nk = K / 32;
    loadA(0); loadB(0);
    storeA(0); storeB(0);
    __syncthreads();

    int buf = 0;
    for (int kt = 0; kt < nk; kt++) {
        const bool pref = (kt + 1 < nk);
        if (pref) { loadA(kt + 1); loadB(kt + 1); }
        compute(buf);
        if (pref) { storeA(buf ^ 1); storeB(buf ^ 1); }
        __syncthreads();
        buf ^= 1;
    }

    // epilogue: c0/c1 at (r0, 2lc..2lc+1), c2/c3 at (r0+8, same cols)
    #pragma unroll
    for (int i = 0; i < 2; i++) {
        const int r0 = bm0 + wm0 + i * 16 + lr;
        const float bv0 = bias ? bias[r0] : 0.f;
        const float bv1 = bias ? bias[r0 + 8] : 0.f;
        float* C0 = C + (size_t)r0 * N + bn0 + wn0 + 2 * lc;
        float* C1 = C + (size_t)(r0 + 8) * N + bn0 + wn0 + 2 * lc;
        const float* R0 = resid ? resid + (size_t)r0 * N + bn0 + wn0 + 2 * lc : (const float*)0;
        const float* R1 = resid ? resid + (size_t)(r0 + 8) * N + bn0 + wn0 + 2 * lc : (const float*)0;
        #pragma unroll
        for (int j = 0; j < 8; j++) {
            float2 v0 = make_float2(acc[i][j][0] * alpha + bv0,
                                    acc[i][j][1] * alpha + bv0);
            float2 v1 = make_float2(acc[i][j][2] * alpha + bv1,
                                    acc[i][j][3] * alpha + bv1);
            if (resid) {
                float2 q0 = *(const float2*)(R0 + j * 8);
                float2 q1 = *(const float2*)(R1 + j * 8);
                v0.x += q0.x; v0.y += q0.y;
                v1.x += q1.x; v1.y += q1.y;
            }
            *(float2*)(C0 + j * 8) = v0;
            *(float2*)(C1 + j * 8) = v1;
        }
    }
}

// ---------------------------------------------------------------------------
// Row softmax over 4096 columns, in place. One block (256 thr) per row.
// ---------------------------------------------------------------------------
__global__ __launch_bounds__(256) void softmax_kernel(float* __restrict__ s)
{
    float* p = s + (size_t)blockIdx.x * HW;
    const int tid = threadIdx.x;

    float4 v[4];
    #pragma unroll
    for (int i = 0; i < 4; i++) v[i] = *(const float4*)(p + i * 1024 + tid * 4);

    float m = -1e30f;
    #pragma unroll
    for (int i = 0; i < 4; i++)
        m = fmaxf(m, fmaxf(fmaxf(v[i].x, v[i].y), fmaxf(v[i].z, v[i].w)));

    __shared__ float red[8];
    #pragma unroll
    for (int o = 16; o > 0; o >>= 1) m = fmaxf(m, __shfl_xor_sync(0xffffffffu, m, o));
    if ((tid & 31) == 0) red[tid >> 5] = m;
    __syncthreads();
    m = red[0];
    #pragma unroll
    for (int i = 1; i < 8; i++) m = fmaxf(m, red[i]);
    __syncthreads();

    float sum = 0.f;
    #pragma unroll
    for (int i = 0; i < 4; i++) {
        v[i].x = __expf(v[i].x - m);
        v[i].y = __expf(v[i].y - m);
        v[i].z = __expf(v[i].z - m);
        v[i].w = __expf(v[i].w - m);
        sum += v[i].x + v[i].y + v[i].z + v[i].w;
    }
    #pragma unroll
    for (int o = 16; o > 0; o >>= 1) sum += __shfl_xor_sync(0xffffffffu, sum, o);
    if ((tid & 31) == 0) red[tid >> 5] = sum;
    __syncthreads();
    sum = 0.f;
    #pragma unroll
    for (int i = 0; i < 8; i++) sum += red[i];

    const float inv = 1.f / sum;
    #pragma unroll
    for (int i = 0; i < 4; i++) {
        v[i].x *= inv; v[i].y *= inv; v[i].z *= inv; v[i].w *= inv;
        *(float4*)(p + i * 1024 + tid * 4) = v[i];
    }
}

// ---------------------------------------------------------------------------
// Launcher
// ---------------------------------------------------------------------------
extern "C" void kernel_launch(void* const* d_in, const int* in_sizes, int n_in,
                              void* d_out, int out_size)
{
    (void)in_sizes; (void)n_in; (void)out_size;
    const float* x    = (const float*)d_in[0];
    const float* gn_w = (const float*)d_in[1];
    const float* gn_b = (const float*)d_in[2];
    const float* wq   = (const float*)d_in[3];
    const float* bq   = (const float*)d_in[4];
    const float* wk   = (const float*)d_in[5];
    const float* bk   = (const float*)d_in[6];
    const float* wv   = (const float*)d_in[7];
    const float* bv   = (const float*)d_in[8];
    const float* wo   = (const float*)d_in[9];
    const float* bo   = (const float*)d_in[10];
    float* out = (float*)d_out;

    float *h_, *q, *k, *v, *o, *s;
    cudaGetSymbolAddress((void**)&h_, g_h);
    cudaGetSymbolAddress((void**)&q,  g_q);
    cudaGetSymbolAddress((void**)&k,  g_k);
    cudaGetSymbolAddress((void**)&v,  g_v);
    cudaGetSymbolAddress((void**)&o,  g_o);
    cudaGetSymbolAddress((void**)&s,  g_s);

    const int SMEM = 65536;
    cudaFuncSetAttribute(mmagemm<0, 0>, cudaFuncAttributeMaxDynamicSharedMemorySize, SMEM);
    cudaFuncSetAttribute(mmagemm<1, 0>, cudaFuncAttributeMaxDynamicSharedMemorySize, SMEM);
    cudaFuncSetAttribute(mmagemm<0, 1>, cudaFuncAttributeMaxDynamicSharedMemorySize, SMEM);

    const long long SC = (long long)C512 * HW;   // per-batch stride for [c][s]
    const long long SS = (long long)HW * HW;     // per-batch stride for scores
    const float scale = 0.044194173824159216f;   // 512^-0.5

    groupnorm_kernel<<<B4 * NG, 256>>>(x, gn_w, gn_b, h_);

    dim3 gQKV(HW / 128, C512 / 128, B4);         // (32, 4, 4)
    mmagemm<0, 0><<<gQKV, 256, SMEM>>>(C512, HW, C512, wq, 0, h_, SC, q, SC, bq, nullptr, 0, 1.f);
    mmagemm<0, 0><<<gQKV, 256, SMEM>>>(C512, HW, C512, wk, 0, h_, SC, k, SC, bk, nullptr, 0, 1.f);
    mmagemm<0, 0><<<gQKV, 256, SMEM>>>(C512, HW, C512, wv, 0, h_, SC, v, SC, bv, nullptr, 0, 1.f);

    dim3 gS(HW / 128, HW / 128, B4);             // (32, 32, 4)
    mmagemm<1, 0><<<gS, 256, SMEM>>>(HW, HW, C512, q, SC, k, SC, s, SS, nullptr, nullptr, 0, scale);

    softmax_kernel<<<B4 * HW, 256>>>(s);

    mmagemm<0, 1><<<gQKV, 256, SMEM>>>(C512, HW, HW, v, SC, s, SS, o, SC, nullptr, nullptr, 0, 1.f);

    mmagemm<0, 0><<<gQKV, 256, SMEM>>>(C512, HW, C512, wo, 0, o, SC, out, SC, bo, x, SC, 1.f);
}

// round 4
// speedup vs baseline: 3.4933x; 1.5743x over previous
#include <cuda_runtime.h>
#include <math.h>
#include <stdint.h>

// ---------------------------------------------------------------------------
// Problem constants
// ---------------------------------------------------------------------------
#define B4 4
#define C512 512
#define HW 4096
#define NG 32

// Scratch (device globals — no runtime allocation allowed)
__device__ float g_h[(size_t)B4 * C512 * HW];
__device__ float g_q[(size_t)B4 * C512 * HW];
__device__ float g_k[(size_t)B4 * C512 * HW];
__device__ float g_v[(size_t)B4 * C512 * HW];
__device__ float g_o[(size_t)B4 * C512 * HW];
__device__ float g_s[(size_t)B4 * HW * HW];     // 256 MB scores/attn

// ---------------------------------------------------------------------------
// GroupNorm (negligible time)
// ---------------------------------------------------------------------------
__global__ __launch_bounds__(256) void groupnorm_kernel(
    const float* __restrict__ x, const float* __restrict__ gamma,
    const float* __restrict__ beta, float* __restrict__ out)
{
    const int GSZ = (C512 / NG) * HW;  // 65536
    int b = blockIdx.x >> 5;
    int g = blockIdx.x & 31;
    const float* xp = x + ((size_t)b * C512 + g * (C512 / NG)) * HW;
    float* op = out + ((size_t)b * C512 + g * (C512 / NG)) * HW;

    float s = 0.f, sq = 0.f;
    for (int i = threadIdx.x * 4; i < GSZ; i += blockDim.x * 4) {
        float4 v = *(const float4*)(xp + i);
        s  += v.x + v.y + v.z + v.w;
        sq += v.x * v.x + v.y * v.y + v.z * v.z + v.w * v.w;
    }
    __shared__ float red0[8], red1[8];
    #pragma unroll
    for (int o = 16; o > 0; o >>= 1) {
        s  += __shfl_xor_sync(0xffffffffu, s, o);
        sq += __shfl_xor_sync(0xffffffffu, sq, o);
    }
    if ((threadIdx.x & 31) == 0) { red0[threadIdx.x >> 5] = s; red1[threadIdx.x >> 5] = sq; }
    __syncthreads();
    s = 0.f; sq = 0.f;
    #pragma unroll
    for (int i = 0; i < 8; i++) { s += red0[i]; sq += red1[i]; }
    float mean = s / GSZ;
    float var  = sq / GSZ - mean * mean;
    float rstd = rsqrtf(var + 1e-6f);

    for (int i = threadIdx.x * 4; i < GSZ; i += blockDim.x * 4) {
        int c = g * (C512 / NG) + (i >> 12);
        float w  = gamma[c] * rstd;
        float bb = beta[c] - mean * w;
        float4 v = *(const float4*)(xp + i);
        v.x = v.x * w + bb; v.y = v.y * w + bb; v.z = v.z * w + bb; v.w = v.w * w + bb;
        *(float4*)(op + i) = v;
    }
}

// ---------------------------------------------------------------------------
// bf16 tensor-core GEMM (fp32 in gmem, bf16 in smem, fp32 accumulate).
// C[m][n] = alpha * sum_k A(m,k)*B(k,n) + bias[m] + resid[m][n]
// TA=0: A row-major MxK (lda=K). TA=1: A stored KxM (lda=M).
// TB=0: B row-major KxN (ldb=N). TB=1: B stored NxK (ldb=K).
// Tiles: BM=BN=128, BK=32. 256 threads, warp grid 4(m) x 2(n), warp 32x64.
// mma.sync.m16n8k16.bf16. smem per operand: [128 rows][16 kpairs] uint32,
// swizzle col' = kpair ^ ((row&7)<<1)  -> conflict-free STS.64 + frag LDS.
// 2 buffers = 32KB static smem, 2 CTAs/SM.
// ---------------------------------------------------------------------------
__device__ __forceinline__ uint32_t packbf(float e0, float e1) {
    uint32_t r;  // low half = e0, high half = e1
    asm("cvt.rn.bf16x2.f32 %0, %1, %2;" : "=r"(r) : "f"(e1), "f"(e0));
    return r;
}

__device__ __forceinline__ void mma_bf16(float* c, const uint32_t* a, const uint32_t* b) {
    asm volatile(
        "mma.sync.aligned.m16n8k16.row.col.f32.bf16.bf16.f32 "
        "{%0,%1,%2,%3}, {%4,%5,%6,%7}, {%8,%9}, {%0,%1,%2,%3};"
        : "+f"(c[0]), "+f"(c[1]), "+f"(c[2]), "+f"(c[3])
        : "r"(a[0]), "r"(a[1]), "r"(a[2]), "r"(a[3]), "r"(b[0]), "r"(b[1]));
}

template <int TA, int TB>
__global__ __launch_bounds__(256, 2) void mmagemm(
    int M, int N, int K,
    const float* __restrict__ A, long long sA,
    const float* __restrict__ B, long long sB,
    float* __restrict__ C, long long sC,
    const float* __restrict__ bias,
    const float* __restrict__ resid, long long sR,
    float alpha)
{
    __shared__ uint32_t As[2][128 * 16];
    __shared__ uint32_t Bs[2][128 * 16];

    const int tid = threadIdx.x;
    const int bm0 = blockIdx.y * 128;
    const int bn0 = blockIdx.x * 128;

    A += (size_t)blockIdx.z * sA;
    B += (size_t)blockIdx.z * sB;
    C += (size_t)blockIdx.z * sC;
    if (resid) resid += (size_t)blockIdx.z * sR;

    const int lda = TA ? M : K;
    const int ldb = TB ? K : N;

    const int lane = tid & 31;
    const int lr = lane >> 2;       // 0..7
    const int lc = lane & 3;        // 0..3
    const int wid = tid >> 5;
    const int wm0 = (wid & 3) * 32;
    const int wn0 = (wid >> 2) * 64;
    const int swf = lr << 1;        // fragment-load swizzle

    // per-thread gmem base pointers
    const float* Ag;
    const float* Bg;
    if (TA == 0) Ag = A + (size_t)(bm0 + (tid >> 3)) * lda + (tid & 7) * 4;
    else         Ag = A + (size_t)((tid >> 7) * 16) * lda + bm0 + (tid & 127);
    if (TB == 1) Bg = B + (size_t)(bn0 + (tid >> 3)) * ldb + (tid & 7) * 4;
    else         Bg = B + (size_t)((tid >> 7) * 16) * ldb + bn0 + (tid & 127);

    uint32_t au[8], bu[8];
    float acc[2][8][4] = {};

    auto loadA = [&](int kt) {
        if (TA == 0) {
            #pragma unroll
            for (int p = 0; p < 4; p++) {
                float4 v = *(const float4*)(Ag + (size_t)p * 32 * lda + (size_t)kt * 32);
                au[p * 2 + 0] = packbf(v.x, v.y);
                au[p * 2 + 1] = packbf(v.z, v.w);
            }
        } else {
            #pragma unroll
            for (int u = 0; u < 8; u++) {
                float e0 = Ag[(size_t)(kt * 32 + 2 * u) * lda];
                float e1 = Ag[(size_t)(kt * 32 + 2 * u + 1) * lda];
                au[u] = packbf(e0, e1);
            }
        }
    };
    auto loadB = [&](int kt) {
        if (TB == 1) {
            #pragma unroll
            for (int p = 0; p < 4; p++) {
                float4 v = *(const float4*)(Bg + (size_t)p * 32 * ldb + (size_t)kt * 32);
                bu[p * 2 + 0] = packbf(v.x, v.y);
                bu[p * 2 + 1] = packbf(v.z, v.w);
            }
        } else {
            #pragma unroll
            for (int u = 0; u < 8; u++) {
                float e0 = Bg[(size_t)(kt * 32 + 2 * u) * ldb];
                float e1 = Bg[(size_t)(kt * 32 + 2 * u + 1) * ldb];
                bu[u] = packbf(e0, e1);
            }
        }
    };
    auto storeA = [&](int buf) {
        uint32_t* dst = As[buf];
        if (TA == 0) {
            const int c2 = (tid & 7) * 2;
            #pragma unroll
            for (int p = 0; p < 4; p++) {
                const int r = (tid >> 3) + p * 32;
                *(uint2*)&dst[r * 16 + (c2 ^ ((r & 7) << 1))] =
                    make_uint2(au[p * 2], au[p * 2 + 1]);
            }
        } else {
            const int m = tid & 127, sx = (m & 7) << 1, kg2 = (tid >> 7) * 8;
            #pragma unroll
            for (int j = 0; j < 4; j++)
                *(uint2*)&dst[m * 16 + ((kg2 + 2 * j) ^ sx)] =
                    make_uint2(au[2 * j], au[2 * j + 1]);
        }
    };
    auto storeB = [&](int buf) {
        uint32_t* dst = Bs[buf];
        if (TB == 1) {
            const int c2 = (tid & 7) * 2;
            #pragma unroll
            for (int p = 0; p < 4; p++) {
                const int r = (tid >> 3) + p * 32;
                *(uint2*)&dst[r * 16 + (c2 ^ ((r & 7) << 1))] =
                    make_uint2(bu[p * 2], bu[p * 2 + 1]);
            }
        } else {
            const int n = tid & 127, sx = (n & 7) << 1, kg2 = (tid >> 7) * 8;
            #pragma unroll
            for (int j = 0; j < 4; j++)
                *(uint2*)&dst[n * 16 + ((kg2 + 2 * j) ^ sx)] =
                    make_uint2(bu[2 * j], bu[2 * j + 1]);
        }
    };
    auto compute = [&](int buf) {
        const uint32_t* Ab = As[buf];
        const uint32_t* Bb = Bs[buf];
        #pragma unroll
        for (int ks = 0; ks < 2; ks++) {
            const int o0 = (ks * 8 + lc) ^ swf;
            const int o1 = o0 ^ 4;
            uint32_t af[2][4], bf[8][2];
            #pragma unroll
            for (int i = 0; i < 2; i++) {
                const int m0 = wm0 + i * 16 + lr;
                af[i][0] = Ab[m0 * 16 + o0];
                af[i][1] = Ab[(m0 + 8) * 16 + o0];
                af[i][2] = Ab[m0 * 16 + o1];
                af[i][3] = Ab[(m0 + 8) * 16 + o1];
            }
            #pragma unroll
            for (int j = 0; j < 8; j++) {
                const int n0 = wn0 + j * 8 + lr;
                bf[j][0] = Bb[n0 * 16 + o0];
                bf[j][1] = Bb[n0 * 16 + o1];
            }
            #pragma unroll
            for (int i = 0; i < 2; i++)
                #pragma unroll
                for (int j = 0; j < 8; j++)
                    mma_bf16(acc[i][j], af[i], bf[j]);
        }
    };

    const int nk = K / 32;
    loadA(0); loadB(0);
    storeA(0); storeB(0);
    __syncthreads();

    int buf = 0;
    for (int kt = 0; kt < nk; kt++) {
        const bool pref = (kt + 1 < nk);
        if (pref) { loadA(kt + 1); loadB(kt + 1); }
        compute(buf);
        if (pref) { storeA(buf ^ 1); storeB(buf ^ 1); }
        __syncthreads();
        buf ^= 1;
    }

    // epilogue: c0/c1 at (r0, 2lc..2lc+1), c2/c3 at (r0+8, same cols)
    #pragma unroll
    for (int i = 0; i < 2; i++) {
        const int r0 = bm0 + wm0 + i * 16 + lr;
        const float bv0 = bias ? bias[r0] : 0.f;
        const float bv1 = bias ? bias[r0 + 8] : 0.f;
        float* C0 = C + (size_t)r0 * N + bn0 + wn0 + 2 * lc;
        float* C1 = C + (size_t)(r0 + 8) * N + bn0 + wn0 + 2 * lc;
        const float* R0 = resid ? resid + (size_t)r0 * N + bn0 + wn0 + 2 * lc : (const float*)0;
        const float* R1 = resid ? resid + (size_t)(r0 + 8) * N + bn0 + wn0 + 2 * lc : (const float*)0;
        #pragma unroll
        for (int j = 0; j < 8; j++) {
            float2 v0 = make_float2(acc[i][j][0] * alpha + bv0,
                                    acc[i][j][1] * alpha + bv0);
            float2 v1 = make_float2(acc[i][j][2] * alpha + bv1,
                                    acc[i][j][3] * alpha + bv1);
            if (resid) {
                float2 q0 = *(const float2*)(R0 + j * 8);
                float2 q1 = *(const float2*)(R1 + j * 8);
                v0.x += q0.x; v0.y += q0.y;
                v1.x += q1.x; v1.y += q1.y;
            }
            *(float2*)(C0 + j * 8) = v0;
            *(float2*)(C1 + j * 8) = v1;
        }
    }
}

// ---------------------------------------------------------------------------
// Row softmax over 4096 columns, in place. One block (256 thr) per row.
// ---------------------------------------------------------------------------
__global__ __launch_bounds__(256) void softmax_kernel(float* __restrict__ s)
{
    float* p = s + (size_t)blockIdx.x * HW;
    const int tid = threadIdx.x;

    float4 v[4];
    #pragma unroll
    for (int i = 0; i < 4; i++) v[i] = *(const float4*)(p + i * 1024 + tid * 4);

    float m = -1e30f;
    #pragma unroll
    for (int i = 0; i < 4; i++)
        m = fmaxf(m, fmaxf(fmaxf(v[i].x, v[i].y), fmaxf(v[i].z, v[i].w)));

    __shared__ float red[8];
    #pragma unroll
    for (int o = 16; o > 0; o >>= 1) m = fmaxf(m, __shfl_xor_sync(0xffffffffu, m, o));
    if ((tid & 31) == 0) red[tid >> 5] = m;
    __syncthreads();
    m = red[0];
    #pragma unroll
    for (int i = 1; i < 8; i++) m = fmaxf(m, red[i]);
    __syncthreads();

    float sum = 0.f;
    #pragma unroll
    for (int i = 0; i < 4; i++) {
        v[i].x = __expf(v[i].x - m);
        v[i].y = __expf(v[i].y - m);
        v[i].z = __expf(v[i].z - m);
        v[i].w = __expf(v[i].w - m);
        sum += v[i].x + v[i].y + v[i].z + v[i].w;
    }
    #pragma unroll
    for (int o = 16; o > 0; o >>= 1) sum += __shfl_xor_sync(0xffffffffu, sum, o);
    if ((tid & 31) == 0) red[tid >> 5] = sum;
    __syncthreads();
    sum = 0.f;
    #pragma unroll
    for (int i = 0; i < 8; i++) sum += red[i];

    const float inv = 1.f / sum;
    #pragma unroll
    for (int i = 0; i < 4; i++) {
        v[i].x *= inv; v[i].y *= inv; v[i].z *= inv; v[i].w *= inv;
        *(float4*)(p + i * 1024 + tid * 4) = v[i];
    }
}

// ---------------------------------------------------------------------------
// Launcher
// ---------------------------------------------------------------------------
extern "C" void kernel_launch(void* const* d_in, const int* in_sizes, int n_in,
                              void* d_out, int out_size)
{
    (void)in_sizes; (void)n_in; (void)out_size;
    const float* x    = (const float*)d_in[0];
    const float* gn_w = (const float*)d_in[1];
    const float* gn_b = (const float*)d_in[2];
    const float* wq   = (const float*)d_in[3];
    const float* bq   = (const float*)d_in[4];
    const float* wk   = (const float*)d_in[5];
    const float* bk   = (const float*)d_in[6];
    const float* wv   = (const float*)d_in[7];
    const float* bv   = (const float*)d_in[8];
    const float* wo   = (const float*)d_in[9];
    const float* bo   = (const float*)d_in[10];
    float* out = (float*)d_out;

    float *h_, *q, *k, *v, *o, *s;
    cudaGetSymbolAddress((void**)&h_, g_h);
    cudaGetSymbolAddress((void**)&q,  g_q);
    cudaGetSymbolAddress((void**)&k,  g_k);
    cudaGetSymbolAddress((void**)&v,  g_v);
    cudaGetSymbolAddress((void**)&o,  g_o);
    cudaGetSymbolAddress((void**)&s,  g_s);

    const long long SC = (long long)C512 * HW;   // per-batch stride for [c][s]
    const long long SS = (long long)HW * HW;     // per-batch stride for scores
    const float scale = 0.044194173824159216f;   // 512^-0.5

    groupnorm_kernel<<<B4 * NG, 256>>>(x, gn_w, gn_b, h_);

    dim3 gQKV(HW / 128, C512 / 128, B4);         // (32, 4, 4)
    mmagemm<0, 0><<<gQKV, 256>>>(C512, HW, C512, wq, 0, h_, SC, q, SC, bq, nullptr, 0, 1.f);
    mmagemm<0, 0><<<gQKV, 256>>>(C512, HW, C512, wk, 0, h_, SC, k, SC, bk, nullptr, 0, 1.f);
    mmagemm<0, 0><<<gQKV, 256>>>(C512, HW, C512, wv, 0, h_, SC, v, SC, bv, nullptr, 0, 1.f);

    dim3 gS(HW / 128, HW / 128, B4);             // (32, 32, 4)
    mmagemm<1, 0><<<gS, 256>>>(HW, HW, C512, q, SC, k, SC, s, SS, nullptr, nullptr, 0, scale);

    softmax_kernel<<<B4 * HW, 256>>>(s);

    mmagemm<0, 1><<<gQKV, 256>>>(C512, HW, HW, v, SC, s, SS, o, SC, nullptr, nullptr, 0, 1.f);

    mmagemm<0, 0><<<gQKV, 256>>>(C512, HW, C512, wo, 0, o, SC, out, SC, bo, x, SC, 1.f);
}

// round 5
// speedup vs baseline: 5.6050x; 1.6045x over previous
#include <cuda_runtime.h>
#include <cuda_bf16.h>
#include <math.h>
#include <stdint.h>

#define B4 4
#define C512 512
#define HW 4096
#define NG 32
typedef __nv_bfloat16 bf16;

// ---------------------------------------------------------------------------
// Scratch (device globals — no runtime allocation allowed)
// ---------------------------------------------------------------------------
__device__ bf16 g_h[(size_t)B4 * C512 * HW];
__device__ bf16 g_q[(size_t)B4 * C512 * HW];
__device__ bf16 g_k[(size_t)B4 * C512 * HW];
__device__ bf16 g_v[(size_t)B4 * C512 * HW];
__device__ bf16 g_o[(size_t)B4 * C512 * HW];
__device__ bf16 g_p[(size_t)B4 * HW * HW];      // 128 MB bf16 attn
__device__ float g_s[(size_t)B4 * HW * HW];     // 256 MB fp32 scores
__device__ bf16 g_w[4 * C512 * C512];           // bf16 weights

// ---------------------------------------------------------------------------
// Helpers
// ---------------------------------------------------------------------------
__device__ __forceinline__ uint32_t packbf(float e0, float e1) {
    uint32_t r;  // low half = e0, high half = e1
    asm("cvt.rn.bf16x2.f32 %0, %1, %2;" : "=r"(r) : "f"(e1), "f"(e0));
    return r;
}
__device__ __forceinline__ uint32_t cvta_s(const void* p) {
    return (uint32_t)__cvta_generic_to_shared(p);
}
__device__ __forceinline__ void ldsm4(uint32_t* r, uint32_t a) {
    asm volatile("ldmatrix.sync.aligned.m8n8.x4.shared.b16 {%0,%1,%2,%3}, [%4];"
                 : "=r"(r[0]), "=r"(r[1]), "=r"(r[2]), "=r"(r[3]) : "r"(a));
}
__device__ __forceinline__ void ldsm4t(uint32_t* r, uint32_t a) {
    asm volatile("ldmatrix.sync.aligned.m8n8.x4.trans.shared.b16 {%0,%1,%2,%3}, [%4];"
                 : "=r"(r[0]), "=r"(r[1]), "=r"(r[2]), "=r"(r[3]) : "r"(a));
}
__device__ __forceinline__ void cpasync16(uint32_t dst, const void* src) {
    asm volatile("cp.async.cg.shared.global [%0], [%1], 16;" :: "r"(dst), "l"(src));
}
__device__ __forceinline__ void mma_bf16(float* c, const uint32_t* a, const uint32_t* b) {
    asm volatile(
        "mma.sync.aligned.m16n8k16.row.col.f32.bf16.bf16.f32 "
        "{%0,%1,%2,%3}, {%4,%5,%6,%7}, {%8,%9}, {%0,%1,%2,%3};"
        : "+f"(c[0]), "+f"(c[1]), "+f"(c[2]), "+f"(c[3])
        : "r"(a[0]), "r"(a[1]), "r"(a[2]), "r"(a[3]), "r"(b[0]), "r"(b[1]));
}

// ---------------------------------------------------------------------------
// Weight fp32 -> bf16 (runs once per call, 1M elements, negligible)
// ---------------------------------------------------------------------------
__global__ __launch_bounds__(256) void convw_kernel(
    const float* __restrict__ w0, const float* __restrict__ w1,
    const float* __restrict__ w2, const float* __restrict__ w3,
    bf16* __restrict__ out)
{
    int i = blockIdx.x * 256 + threadIdx.x;          // grid 4096 -> 1048576
    const float* src = (i < 262144) ? w0 : (i < 524288) ? w1
                      : (i < 786432) ? w2 : w3;
    out[i] = __float2bfloat16(src[i & 262143]);
}

// ---------------------------------------------------------------------------
// GroupNorm -> bf16 output
// ---------------------------------------------------------------------------
__global__ __launch_bounds__(256) void groupnorm_kernel(
    const float* __restrict__ x, const float* __restrict__ gamma,
    const float* __restrict__ beta, bf16* __restrict__ out)
{
    const int GSZ = (C512 / NG) * HW;  // 65536
    int b = blockIdx.x >> 5;
    int g = blockIdx.x & 31;
    const float* xp = x + ((size_t)b * C512 + g * (C512 / NG)) * HW;
    bf16* op = out + ((size_t)b * C512 + g * (C512 / NG)) * HW;

    float s = 0.f, sq = 0.f;
    for (int i = threadIdx.x * 4; i < GSZ; i += blockDim.x * 4) {
        float4 v = *(const float4*)(xp + i);
        s  += v.x + v.y + v.z + v.w;
        sq += v.x * v.x + v.y * v.y + v.z * v.z + v.w * v.w;
    }
    __shared__ float red0[8], red1[8];
    #pragma unroll
    for (int o = 16; o > 0; o >>= 1) {
        s  += __shfl_xor_sync(0xffffffffu, s, o);
        sq += __shfl_xor_sync(0xffffffffu, sq, o);
    }
    if ((threadIdx.x & 31) == 0) { red0[threadIdx.x >> 5] = s; red1[threadIdx.x >> 5] = sq; }
    __syncthreads();
    s = 0.f; sq = 0.f;
    #pragma unroll
    for (int i = 0; i < 8; i++) { s += red0[i]; sq += red1[i]; }
    float mean = s / GSZ;
    float var  = sq / GSZ - mean * mean;
    float rstd = rsqrtf(var + 1e-6f);

    for (int i = threadIdx.x * 4; i < GSZ; i += blockDim.x * 4) {
        int c = g * (C512 / NG) + (i >> 12);
        float w  = gamma[c] * rstd;
        float bb = beta[c] - mean * w;
        float4 v = *(const float4*)(xp + i);
        uint2 pk;
        pk.x = packbf(v.x * w + bb, v.y * w + bb);
        pk.y = packbf(v.z * w + bb, v.w * w + bb);
        *(uint2*)(op + i) = pk;
    }
}

// ---------------------------------------------------------------------------
// bf16 tensor-core GEMM, cp.async 3-stage pipeline + ldmatrix fragments.
// C[m][n] = alpha * sum_k A(m,k)*B(k,n) + bias[m] (+ resid[m][n] fp32 path)
// TA=0: A row-major MxK (lda=K).  TA=1: A stored KxM (lda=M)  [ldmatrix.trans]
// TB=1: B stored NxK (ldb=K).     TB=0: B row-major KxN (ldb=N) [trans]
// Block 128x128xBK32, 256 thr, warps 4(m)x2(n), warp tile 32x64.
// smem/operand/stage 8KB. Row-major class: [r][32k] 64B rows, chunk^=(r>>1)&3.
// K-major class: [k][128mn] 256B rows, chunk^=(k&7). OUTBF: bf16 C.
// ---------------------------------------------------------------------------
template <int TA, int TB, int OUTBF>
__global__ __launch_bounds__(256, 2) void bfgemm(
    int M, int N, int K,
    const bf16* __restrict__ A, long long sA,
    const bf16* __restrict__ B, long long sB,
    void* __restrict__ Cv, long long sC,
    const float* __restrict__ bias,
    const float* __restrict__ resid, long long sR,
    float alpha)
{
    extern __shared__ bf16 smbuf[];
    bf16* Ash = smbuf;              // [3][4096]
    bf16* Bsh = smbuf + 3 * 4096;

    const int tid = threadIdx.x, lane = tid & 31, wid = tid >> 5;
    const int bm0 = blockIdx.y * 128, bn0 = blockIdx.x * 128;
    A += (size_t)blockIdx.z * sA;
    B += (size_t)blockIdx.z * sB;

    const int lda = TA ? M : K;
    const int ldb = TB ? K : N;
    const long long stepA = TA ? (long long)32 * lda : 32;
    const long long stepB = TB ? 32 : (long long)32 * ldb;

    const uint32_t As_u = cvta_s(Ash);
    const uint32_t Bs_u = cvta_s(Bsh);

    // cp.async per-thread src pointers / dst offsets (2 x 16B per operand)
    const bf16* aSrc[2]; uint32_t aDst[2];
    const bf16* bSrc[2]; uint32_t bDst[2];
    #pragma unroll
    for (int i = 0; i < 2; i++) {
        const int g = tid + i * 256;
        if (TA == 0) {
            int r = g >> 2, c = g & 3;
            aSrc[i] = A + (size_t)(bm0 + r) * lda + c * 8;
            aDst[i] = (uint32_t)(r * 4 + (c ^ ((r >> 1) & 3))) * 16;
        } else {
            int k = g >> 4, c = g & 15;
            aSrc[i] = A + (size_t)k * lda + bm0 + c * 8;
            aDst[i] = (uint32_t)(k * 16 + (c ^ (k & 7))) * 16;
        }
        if (TB == 1) {
            int r = g >> 2, c = g & 3;
            bSrc[i] = B + (size_t)(bn0 + r) * ldb + c * 8;
            bDst[i] = (uint32_t)(r * 4 + (c ^ ((r >> 1) & 3))) * 16;
        } else {
            int k = g >> 4, c = g & 15;
            bSrc[i] = B + (size_t)k * ldb + bn0 + c * 8;
            bDst[i] = (uint32_t)(k * 16 + (c ^ (k & 7))) * 16;
        }
    }

    // ldmatrix fragment byte offsets
    const int quad = lane >> 3, lrow = lane & 7;
    const int wm0 = (wid & 3) * 32, wn0 = (wid >> 2) * 64;
    uint32_t fA[2][2], fB[2][4];
    #pragma unroll
    for (int ks = 0; ks < 2; ks++) {
        #pragma unroll
        for (int mi = 0; mi < 2; mi++) {
            if (TA == 0) {
                int r = wm0 + mi * 16 + (quad & 1) * 8 + lrow;
                int c = 2 * ks + (quad >> 1);
                fA[ks][mi] = (uint32_t)(r * 4 + (c ^ ((r >> 1) & 3))) * 16;
            } else {
                int k = ks * 16 + (quad >> 1) * 8 + lrow;
                int c = ((wm0 + mi * 16) >> 3) + (quad & 1);
                fA[ks][mi] = (uint32_t)(k * 16 + (c ^ (k & 7))) * 16;
            }
        }
        #pragma unroll
        for (int nj = 0; nj < 4; nj++) {
            if (TB == 1) {
                int r = wn0 + nj * 16 + (quad & 1) * 8 + lrow;
                int c = 2 * ks + (quad >> 1);
                fB[ks][nj] = (uint32_t)(r * 4 + (c ^ ((r >> 1) & 3))) * 16;
            } else {
                int k = ks * 16 + (quad >> 1) * 8 + lrow;
                int c = ((wn0 + nj * 16) >> 3) + (quad & 1);
                fB[ks][nj] = (uint32_t)(k * 16 + (c ^ (k & 7))) * 16;
            }
        }
    }

    auto issue = [&](int st, int kt) {
        #pragma unroll
        for (int i = 0; i < 2; i++) {
            cpasync16(As_u + st * 8192 + aDst[i], aSrc[i] + (size_t)kt * stepA);
            cpasync16(Bs_u + st * 8192 + bDst[i], bSrc[i] + (size_t)kt * stepB);
        }
    };

    float acc[2][8][4] = {};
    auto compute = [&](int st) {
        const uint32_t ab = As_u + st * 8192;
        const uint32_t bb = Bs_u + st * 8192;
        #pragma unroll
        for (int ks = 0; ks < 2; ks++) {
            uint32_t a[2][4], b[4][4];
            #pragma unroll
            for (int mi = 0; mi < 2; mi++) {
                if (TA == 0) ldsm4(a[mi], ab + fA[ks][mi]);
                else         ldsm4t(a[mi], ab + fA[ks][mi]);
            }
            #pragma unroll
            for (int nj = 0; nj < 4; nj++) {
                if (TB == 1) ldsm4(b[nj], bb + fB[ks][nj]);
                else         ldsm4t(b[nj], bb + fB[ks][nj]);
            }
            #pragma unroll
            for (int mi = 0; mi < 2; mi++)
                #pragma unroll
                for (int nj = 0; nj < 4; nj++) {
                    uint32_t bl[2] = {b[nj][0], b[nj][2]};
                    uint32_t bh[2] = {b[nj][1], b[nj][3]};
                    mma_bf16(acc[mi][nj * 2 + 0], a[mi], bl);
                    mma_bf16(acc[mi][nj * 2 + 1], a[mi], bh);
                }
        }
    };

    const int nk = K / 32;
    issue(0, 0); asm volatile("cp.async.commit_group;" ::: "memory");
    issue(1, 1); asm volatile("cp.async.commit_group;" ::: "memory");

    for (int kt = 0; kt < nk; kt++) {
        asm volatile("cp.async.wait_group 1;" ::: "memory");
        __syncthreads();
        compute(kt % 3);
        if (kt + 2 < nk) issue((kt + 2) % 3, kt + 2);
        asm volatile("cp.async.commit_group;" ::: "memory");
    }

    // epilogue: c0/c1 at (r0, 2lc..2lc+1), c2/c3 at (r0+8, same cols)
    const int lr = lane >> 2, lc = lane & 3;
    #pragma unroll
    for (int mi = 0; mi < 2; mi++) {
        const int r0 = bm0 + wm0 + mi * 16 + lr;
        const float bv0 = bias ? bias[r0] : 0.f;
        const float bv1 = bias ? bias[r0 + 8] : 0.f;
        const int col = bn0 + wn0 + 2 * lc;
        if (OUTBF) {
            bf16* C = (bf16*)Cv + (size_t)blockIdx.z * sC;
            uint32_t* C0 = (uint32_t*)(C + (size_t)r0 * N + col);
            uint32_t* C1 = (uint32_t*)(C + (size_t)(r0 + 8) * N + col);
            #pragma unroll
            for (int j = 0; j < 8; j++) {
                C0[j * 4] = packbf(acc[mi][j][0] * alpha + bv0,
                                   acc[mi][j][1] * alpha + bv0);
                C1[j * 4] = packbf(acc[mi][j][2] * alpha + bv1,
                                   acc[mi][j][3] * alpha + bv1);
            }
        } else {
            float* C = (float*)Cv + (size_t)blockIdx.z * sC;
            float* C0 = C + (size_t)r0 * N + col;
            float* C1 = C + (size_t)(r0 + 8) * N + col;
            const float* R0 = resid ? resid + (size_t)blockIdx.z * sR + (size_t)r0 * N + col : (const float*)0;
            const float* R1 = resid ? resid + (size_t)blockIdx.z * sR + (size_t)(r0 + 8) * N + col : (const float*)0;
            #pragma unroll
            for (int j = 0; j < 8; j++) {
                float2 v0 = make_float2(acc[mi][j][0] * alpha + bv0,
                                        acc[mi][j][1] * alpha + bv0);
                float2 v1 = make_float2(acc[mi][j][2] * alpha + bv1,
                                        acc[mi][j][3] * alpha + bv1);
                if (resid) {
                    float2 q0 = *(const float2*)(R0 + j * 8);
                    float2 q1 = *(const float2*)(R1 + j * 8);
                    v0.x += q0.x; v0.y += q0.y;
                    v1.x += q1.x; v1.y += q1.y;
                }
                *(float2*)(C0 + j * 8) = v0;
                *(float2*)(C1 + j * 8) = v1;
            }
        }
    }
}

// ---------------------------------------------------------------------------
// Row softmax: fp32 scores in, bf16 attn out. One block (256 thr) per row.
// ---------------------------------------------------------------------------
__global__ __launch_bounds__(256) void softmax_kernel(
    const float* __restrict__ s, bf16* __restrict__ p)
{
    const float* sp = s + (size_t)blockIdx.x * HW;
    bf16* pp = p + (size_t)blockIdx.x * HW;
    const int tid = threadIdx.x;

    float4 v[4];
    #pragma unroll
    for (int i = 0; i < 4; i++) v[i] = *(const float4*)(sp + i * 1024 + tid * 4);

    float m = -1e30f;
    #pragma unroll
    for (int i = 0; i < 4; i++)
        m = fmaxf(m, fmaxf(fmaxf(v[i].x, v[i].y), fmaxf(v[i].z, v[i].w)));

    __shared__ float red[8];
    #pragma unroll
    for (int o = 16; o > 0; o >>= 1) m = fmaxf(m, __shfl_xor_sync(0xffffffffu, m, o));
    if ((tid & 31) == 0) red[tid >> 5] = m;
    __syncthreads();
    m = red[0];
    #pragma unroll
    for (int i = 1; i < 8; i++) m = fmaxf(m, red[i]);
    __syncthreads();

    float sum = 0.f;
    #pragma unroll
    for (int i = 0; i < 4; i++) {
        v[i].x = __expf(v[i].x - m);
        v[i].y = __expf(v[i].y - m);
        v[i].z = __expf(v[i].z - m);
        v[i].w = __expf(v[i].w - m);
        sum += v[i].x + v[i].y + v[i].z + v[i].w;
    }
    #pragma unroll
    for (int o = 16; o > 0; o >>= 1) sum += __shfl_xor_sync(0xffffffffu, sum, o);
    if ((tid & 31) == 0) red[tid >> 5] = sum;
    __syncthreads();
    sum = 0.f;
    #pragma unroll
    for (int i = 0; i < 8; i++) sum += red[i];

    const float inv = 1.f / sum;
    #pragma unroll
    for (int i = 0; i < 4; i++) {
        uint2 pk;
        pk.x = packbf(v[i].x * inv, v[i].y * inv);
        pk.y = packbf(v[i].z * inv, v[i].w * inv);
        *(uint2*)(pp + i * 1024 + tid * 4) = pk;
    }
}

// ---------------------------------------------------------------------------
// Launcher
// ---------------------------------------------------------------------------
extern "C" void kernel_launch(void* const* d_in, const int* in_sizes, int n_in,
                              void* d_out, int out_size)
{
    (void)in_sizes; (void)n_in; (void)out_size;
    const float* x    = (const float*)d_in[0];
    const float* gn_w = (const float*)d_in[1];
    const float* gn_b = (const float*)d_in[2];
    const float* wq   = (const float*)d_in[3];
    const float* bq   = (const float*)d_in[4];
    const float* wk   = (const float*)d_in[5];
    const float* bk   = (const float*)d_in[6];
    const float* wv   = (const float*)d_in[7];
    const float* bv   = (const float*)d_in[8];
    const float* wo   = (const float*)d_in[9];
    const float* bo   = (const float*)d_in[10];
    float* out = (float*)d_out;

    bf16 *h_, *q, *k, *v, *o, *p, *w;
    float* s;
    cudaGetSymbolAddress((void**)&h_, g_h);
    cudaGetSymbolAddress((void**)&q,  g_q);
    cudaGetSymbolAddress((void**)&k,  g_k);
    cudaGetSymbolAddress((void**)&v,  g_v);
    cudaGetSymbolAddress((void**)&o,  g_o);
    cudaGetSymbolAddress((void**)&p,  g_p);
    cudaGetSymbolAddress((void**)&s,  g_s);
    cudaGetSymbolAddress((void**)&w,  g_w);

    const int SMEM = 49152;
    cudaFuncSetAttribute(bfgemm<0, 0, 1>, cudaFuncAttributeMaxDynamicSharedMemorySize, SMEM);
    cudaFuncSetAttribute(bfgemm<1, 0, 0>, cudaFuncAttributeMaxDynamicSharedMemorySize, SMEM);
    cudaFuncSetAttribute(bfgemm<0, 1, 1>, cudaFuncAttributeMaxDynamicSharedMemorySize, SMEM);
    cudaFuncSetAttribute(bfgemm<0, 0, 0>, cudaFuncAttributeMaxDynamicSharedMemorySize, SMEM);

    const long long SC = (long long)C512 * HW;   // per-batch stride [c][s]
    const long long SS = (long long)HW * HW;     // per-batch stride scores/attn
    const int WSZ = C512 * C512;
    const float scale = 0.044194173824159216f;   // 512^-0.5

    convw_kernel<<<4096, 256>>>(wq, wk, wv, wo, w);
    groupnorm_kernel<<<B4 * NG, 256>>>(x, gn_w, gn_b, h_);

    dim3 gQKV(HW / 128, C512 / 128, B4);         // (32, 4, 4)
    bfgemm<0, 0, 1><<<gQKV, 256, SMEM>>>(C512, HW, C512, w + 0 * WSZ, 0, h_, SC, q, SC, bq, nullptr, 0, 1.f);
    bfgemm<0, 0, 1><<<gQKV, 256, SMEM>>>(C512, HW, C512, w + 1 * WSZ, 0, h_, SC, k, SC, bk, nullptr, 0, 1.f);
    bfgemm<0, 0, 1><<<gQKV, 256, SMEM>>>(C512, HW, C512, w + 2 * WSZ, 0, h_, SC, v, SC, bv, nullptr, 0, 1.f);

    dim3 gS(HW / 128, HW / 128, B4);             // (32, 32, 4)
    bfgemm<1, 0, 0><<<gS, 256, SMEM>>>(HW, HW, C512, q, SC, k, SC, s, SS, nullptr, nullptr, 0, scale);

    softmax_kernel<<<B4 * HW, 256>>>(s, p);

    bfgemm<0, 1, 1><<<gQKV, 256, SMEM>>>(C512, HW, HW, v, SC, p, SS, o, SC, nullptr, nullptr, 0, 1.f);

    bfgemm<0, 0, 0><<<gQKV, 256, SMEM>>>(C512, HW, C512, w + 3 * WSZ, 0, o, SC, out, SC, bo, x, SC, 1.f);
}

// round 7
// speedup vs baseline: 6.1693x; 1.1007x over previous
#include <cuda_runtime.h>
#include <cuda_bf16.h>
#include <math.h>
#include <stdint.h>

#define B4 4
#define C512 512
#define HW 4096
#define NG 32
typedef __nv_bfloat16 bf16;

// ---------------------------------------------------------------------------
// Scratch (device globals — no runtime allocation allowed)
// g_qkv: [b][1536][s]  rows 0..511=q, 512..1023=k, 1024..1535=v  (bf16)
// ---------------------------------------------------------------------------
__device__ bf16 g_h  [(size_t)B4 * C512 * HW];          // groupnorm out [b][c][s]
__device__ bf16 g_qkv[(size_t)B4 * 3 * C512 * HW];      // fused qkv
__device__ bf16 g_o  [(size_t)B4 * C512 * HW];          // attn out [b][c][s]
__device__ bf16 g_p  [(size_t)B4 * HW * HW];            // e = exp(scores) bf16
__device__ bf16 g_w  [4 * C512 * C512];                 // bf16 weights q,k,v,o
__device__ float g_bqkv[3 * C512];                      // concat biases
__device__ float g_ps[(size_t)B4 * HW * 32];            // per-(row, jtile) partial sums
__device__ float g_ri[(size_t)B4 * HW];                 // 1/rowsum

// ---------------------------------------------------------------------------
// Helpers
// ---------------------------------------------------------------------------
__device__ __forceinline__ uint32_t packbf(float e0, float e1) {
    uint32_t r;  // low half = e0, high half = e1
    asm("cvt.rn.bf16x2.f32 %0, %1, %2;" : "=r"(r) : "f"(e1), "f"(e0));
    return r;
}
__device__ __forceinline__ uint32_t cvta_s(const void* p) {
    return (uint32_t)__cvta_generic_to_shared(p);
}
__device__ __forceinline__ void ldsm4(uint32_t* r, uint32_t a) {
    asm volatile("ldmatrix.sync.aligned.m8n8.x4.shared.b16 {%0,%1,%2,%3}, [%4];"
                 : "=r"(r[0]), "=r"(r[1]), "=r"(r[2]), "=r"(r[3]) : "r"(a));
}
__device__ __forceinline__ void ldsm4t(uint32_t* r, uint32_t a) {
    asm volatile("ldmatrix.sync.aligned.m8n8.x4.trans.shared.b16 {%0,%1,%2,%3}, [%4];"
                 : "=r"(r[0]), "=r"(r[1]), "=r"(r[2]), "=r"(r[3]) : "r"(a));
}
__device__ __forceinline__ void cpasync16(uint32_t dst, const void* src) {
    asm volatile("cp.async.cg.shared.global [%0], [%1], 16;" :: "r"(dst), "l"(src));
}
__device__ __forceinline__ void mma_bf16(float* c, const uint32_t* a, const uint32_t* b) {
    asm volatile(
        "mma.sync.aligned.m16n8k16.row.col.f32.bf16.bf16.f32 "
        "{%0,%1,%2,%3}, {%4,%5,%6,%7}, {%8,%9}, {%0,%1,%2,%3};"
        : "+f"(c[0]), "+f"(c[1]), "+f"(c[2]), "+f"(c[3])
        : "r"(a[0]), "r"(a[1]), "r"(a[2]), "r"(a[3]), "r"(b[0]), "r"(b[1]));
}

// ---------------------------------------------------------------------------
// Weight fp32 -> bf16 ; bias concat
// ---------------------------------------------------------------------------
__global__ __launch_bounds__(256) void convw_kernel(
    const float* __restrict__ w0, const float* __restrict__ w1,
    const float* __restrict__ w2, const float* __restrict__ w3,
    bf16* __restrict__ out)
{
    int i = blockIdx.x * 256 + threadIdx.x;
    const float* src = (i < 262144) ? w0 : (i < 524288) ? w1
                      : (i < 786432) ? w2 : w3;
    out[i] = __float2bfloat16(src[i & 262143]);
}
__global__ __launch_bounds__(256) void convb_kernel(
    const float* __restrict__ b0, const float* __restrict__ b1,
    const float* __restrict__ b2, float* __restrict__ out)
{
    int i = blockIdx.x * 256 + threadIdx.x;   // grid 6 -> 1536
    out[i] = (i < 512) ? b0[i] : (i < 1024) ? b1[i - 512] : b2[i - 1024];
}

// ---------------------------------------------------------------------------
// GroupNorm -> bf16 [b][c][s]
// ---------------------------------------------------------------------------
__global__ __launch_bounds__(256) void groupnorm_kernel(
    const float* __restrict__ x, const float* __restrict__ gamma,
    const float* __restrict__ beta, bf16* __restrict__ out)
{
    const int GSZ = (C512 / NG) * HW;  // 65536
    int b = blockIdx.x >> 5;
    int g = blockIdx.x & 31;
    const float* xp = x + ((size_t)b * C512 + g * (C512 / NG)) * HW;
    bf16* op = out + ((size_t)b * C512 + g * (C512 / NG)) * HW;

    float s = 0.f, sq = 0.f;
    for (int i = threadIdx.x * 4; i < GSZ; i += blockDim.x * 4) {
        float4 v = *(const float4*)(xp + i);
        s  += v.x + v.y + v.z + v.w;
        sq += v.x * v.x + v.y * v.y + v.z * v.z + v.w * v.w;
    }
    __shared__ float red0[8], red1[8];
    #pragma unroll
    for (int o = 16; o > 0; o >>= 1) {
        s  += __shfl_xor_sync(0xffffffffu, s, o);
        sq += __shfl_xor_sync(0xffffffffu, sq, o);
    }
    if ((threadIdx.x & 31) == 0) { red0[threadIdx.x >> 5] = s; red1[threadIdx.x >> 5] = sq; }
    __syncthreads();
    s = 0.f; sq = 0.f;
    #pragma unroll
    for (int i = 0; i < 8; i++) { s += red0[i]; sq += red1[i]; }
    float mean = s / GSZ;
    float var  = sq / GSZ - mean * mean;
    float rstd = rsqrtf(var + 1e-6f);

    for (int i = threadIdx.x * 4; i < GSZ; i += blockDim.x * 4) {
        int c = g * (C512 / NG) + (i >> 12);
        float w  = gamma[c] * rstd;
        float bb = beta[c] - mean * w;
        float4 v = *(const float4*)(xp + i);
        uint2 pk;
        pk.x = packbf(v.x * w + bb, v.y * w + bb);
        pk.y = packbf(v.z * w + bb, v.w * w + bb);
        *(uint2*)(op + i) = pk;
    }
}

// ---------------------------------------------------------------------------
// bf16 tensor-core GEMM, cp.async 3-stage pipeline + ldmatrix fragments.
// C[m][n] = alpha * sum_k A(m,k)*B(k,n)
// TA=0: A row-major MxK (lda=K).  TA=1: A stored KxM (lda=M)  [ldmatrix.trans]
// TB=1: B stored NxK (ldb=K).     TB=0: B row-major KxN (ldb=N) [trans]
// Block 128x128xBK32, 256 thr, warps 4(m)x2(n), warp tile 32x64.
// EPI: 0 = bias[m] (+resid) normal epilogue
//      1 = p = bf16(exp(alpha*acc)); per-(row,jtile) partial sums -> psum
//      2 = multiply by nsc[n-col] (deferred softmax normalization), bf16 out
// OUTBF: bf16 C (else fp32 + optional resid).
// ---------------------------------------------------------------------------
template <int TA, int TB, int OUTBF, int EPI>
__global__ __launch_bounds__(256, 2) void bfgemm(
    int M, int N, int K,
    const bf16* __restrict__ A, long long sA,
    const bf16* __restrict__ B, long long sB,
    void* __restrict__ Cv, long long sC,
    const float* __restrict__ bias,
    const float* __restrict__ resid, long long sR,
    float* __restrict__ psum,
    const float* __restrict__ nsc,
    float alpha)
{
    extern __shared__ bf16 smbuf[];
    bf16* Ash = smbuf;              // [3][4096]
    bf16* Bsh = smbuf + 3 * 4096;

    const int tid = threadIdx.x, lane = tid & 31, wid = tid >> 5;
    const int bm0 = blockIdx.y * 128, bn0 = blockIdx.x * 128;
    const int bz = blockIdx.z;
    A += (size_t)bz * sA;
    B += (size_t)bz * sB;

    const int lda = TA ? M : K;
    const int ldb = TB ? K : N;
    const long long stepA = TA ? (long long)32 * lda : 32;
    const long long stepB = TB ? 32 : (long long)32 * ldb;

    const uint32_t As_u = cvta_s(Ash);
    const uint32_t Bs_u = cvta_s(Bsh);

    // cp.async per-thread src pointers / dst offsets (2 x 16B per operand)
    const bf16* aSrc[2]; uint32_t aDst[2];
    const bf16* bSrc[2]; uint32_t bDst[2];
    #pragma unroll
    for (int i = 0; i < 2; i++) {
        const int g = tid + i * 256;
        if (TA == 0) {
            int r = g >> 2, c = g & 3;
            aSrc[i] = A + (size_t)(bm0 + r) * lda + c * 8;
            aDst[i] = (uint32_t)(r * 4 + (c ^ ((r >> 1) & 3))) * 16;
        } else {
            int k = g >> 4, c = g & 15;
            aSrc[i] = A + (size_t)k * lda + bm0 + c * 8;
            aDst[i] = (uint32_t)(k * 16 + (c ^ (k & 7))) * 16;
        }
        if (TB == 1) {
            int r = g >> 2, c = g & 3;
            bSrc[i] = B + (size_t)(bn0 + r) * ldb + c * 8;
            bDst[i] = (uint32_t)(r * 4 + (c ^ ((r >> 1) & 3))) * 16;
        } else {
            int k = g >> 4, c = g & 15;
            bSrc[i] = B + (size_t)k * ldb + bn0 + c * 8;
            bDst[i] = (uint32_t)(k * 16 + (c ^ (k & 7))) * 16;
        }
    }

    // ldmatrix fragment byte offsets
    const int quad = lane >> 3, lrow = lane & 7;
    const int wm0 = (wid & 3) * 32, wn0 = (wid >> 2) * 64;
    uint32_t fA[2][2], fB[2][4];
    #pragma unroll
    for (int ks = 0; ks < 2; ks++) {
        #pragma unroll
        for (int mi = 0; mi < 2; mi++) {
            if (TA == 0) {
                int r = wm0 + mi * 16 + (quad & 1) * 8 + lrow;
                int c = 2 * ks + (quad >> 1);
                fA[ks][mi] = (uint32_t)(r * 4 + (c ^ ((r >> 1) & 3))) * 16;
            } else {
                int k = ks * 16 + (quad >> 1) * 8 + lrow;
                int c = ((wm0 + mi * 16) >> 3) + (quad & 1);
                fA[ks][mi] = (uint32_t)(k * 16 + (c ^ (k & 7))) * 16;
            }
        }
        #pragma unroll
        for (int nj = 0; nj < 4; nj++) {
            if (TB == 1) {
                int r = wn0 + nj * 16 + (quad & 1) * 8 + lrow;
                int c = 2 * ks + (quad >> 1);
                fB[ks][nj] = (uint32_t)(r * 4 + (c ^ ((r >> 1) & 3))) * 16;
            } else {
                int k = ks * 16 + (quad >> 1) * 8 + lrow;
                int c = ((wn0 + nj * 16) >> 3) + (quad & 1);
                fB[ks][nj] = (uint32_t)(k * 16 + (c ^ (k & 7))) * 16;
            }
        }
    }

    auto issue = [&](int st, int kt) {
        #pragma unroll
        for (int i = 0; i < 2; i++) {
            cpasync16(As_u + st * 8192 + aDst[i], aSrc[i] + (size_t)kt * stepA);
            cpasync16(Bs_u + st * 8192 + bDst[i], bSrc[i] + (size_t)kt * stepB);
        }
    };

    float acc[2][8][4] = {};
    auto compute = [&](int st) {
        const uint32_t ab = As_u + st * 8192;
        const uint32_t bb = Bs_u + st * 8192;
        #pragma unroll
        for (int ks = 0; ks < 2; ks++) {
            uint32_t a[2][4], b[4][4];
            #pragma unroll
            for (int mi = 0; mi < 2; mi++) {
                if (TA == 0) ldsm4(a[mi], ab + fA[ks][mi]);
                else         ldsm4t(a[mi], ab + fA[ks][mi]);
            }
            #pragma unroll
            for (int nj = 0; nj < 4; nj++) {
                if (TB == 1) ldsm4(b[nj], bb + fB[ks][nj]);
                else         ldsm4t(b[nj], bb + fB[ks][nj]);
            }
            #pragma unroll
            for (int mi = 0; mi < 2; mi++)
                #pragma unroll
                for (int nj = 0; nj < 4; nj++) {
                    uint32_t bl[2] = {b[nj][0], b[nj][2]};
                    uint32_t bh[2] = {b[nj][1], b[nj][3]};
                    mma_bf16(acc[mi][nj * 2 + 0], a[mi], bl);
                    mma_bf16(acc[mi][nj * 2 + 1], a[mi], bh);
                }
        }
    };

    const int nk = K / 32;
    issue(0, 0); asm volatile("cp.async.commit_group;" ::: "memory");
    issue(1, 1); asm volatile("cp.async.commit_group;" ::: "memory");

    for (int kt = 0; kt < nk; kt++) {
        asm volatile("cp.async.wait_group 1;" ::: "memory");
        __syncthreads();
        compute(kt % 3);
        if (kt + 2 < nk) issue((kt + 2) % 3, kt + 2);
        asm volatile("cp.async.commit_group;" ::: "memory");
    }

    // ---------------- epilogue ----------------
    const int lr = lane >> 2, lc = lane & 3;

    if (EPI == 1) {
        // p = bf16(exp(alpha*acc)); partial row sums into psum[(b*HW+row)*32 + jtile]
        __syncthreads();                       // smem reuse for row-sum reduction
        float* ps = (float*)smbuf;             // [128][2]
        bf16* C = (bf16*)Cv + (size_t)bz * sC;
        float rs[2][2];
        #pragma unroll
        for (int mi = 0; mi < 2; mi++) {
            const int r0 = bm0 + wm0 + mi * 16 + lr;
            const int col = bn0 + wn0 + 2 * lc;
            uint32_t* C0 = (uint32_t*)(C + (size_t)r0 * N + col);
            uint32_t* C1 = (uint32_t*)(C + (size_t)(r0 + 8) * N + col);
            float s0 = 0.f, s1 = 0.f;
            #pragma unroll
            for (int j = 0; j < 8; j++) {
                float e00 = __expf(acc[mi][j][0] * alpha);
                float e01 = __expf(acc[mi][j][1] * alpha);
                float e10 = __expf(acc[mi][j][2] * alpha);
                float e11 = __expf(acc[mi][j][3] * alpha);
                C0[j * 4] = packbf(e00, e01);
                C1[j * 4] = packbf(e10, e11);
                s0 += e00 + e01;
                s1 += e10 + e11;
            }
            rs[mi][0] = s0; rs[mi][1] = s1;
        }
        #pragma unroll
        for (int mi = 0; mi < 2; mi++)
            #pragma unroll
            for (int h = 0; h < 2; h++) {
                float v = rs[mi][h];
                v += __shfl_xor_sync(0xffffffffu, v, 1);
                v += __shfl_xor_sync(0xffffffffu, v, 2);
                if (lc == 0)
                    ps[(wm0 + mi * 16 + h * 8 + lr) * 2 + (wn0 >> 6)] = v;
            }
        __syncthreads();
        if (tid < 128) {
            float t = ps[tid * 2 + 0] + ps[tid * 2 + 1];
            psum[((size_t)bz * HW + bm0 + tid) * 32 + blockIdx.x] = t;
        }
        return;
    }

    #pragma unroll
    for (int mi = 0; mi < 2; mi++) {
        const int r0 = bm0 + wm0 + mi * 16 + lr;
        const int col = bn0 + wn0 + 2 * lc;
        if (OUTBF) {
            bf16* C = (bf16*)Cv + (size_t)bz * sC;
            uint32_t* C0 = (uint32_t*)(C + (size_t)r0 * N + col);
            uint32_t* C1 = (uint32_t*)(C + (size_t)(r0 + 8) * N + col);
            const float bv0 = (EPI == 0 && bias) ? bias[r0] : 0.f;
            const float bv1 = (EPI == 0 && bias) ? bias[r0 + 8] : 0.f;
            #pragma unroll
            for (int j = 0; j < 8; j++) {
                float f0 = 1.f, f1 = 1.f;
                if (EPI == 2) {
                    float2 ff = *(const float2*)(nsc + (size_t)bz * HW + col + j * 8);
                    f0 = ff.x; f1 = ff.y;
                }
                C0[j * 4] = packbf(acc[mi][j][0] * alpha * f0 + bv0,
                                   acc[mi][j][1] * alpha * f1 + bv0);
                C1[j * 4] = packbf(acc[mi][j][2] * alpha * f0 + bv1,
                                   acc[mi][j][3] * alpha * f1 + bv1);
            }
        } else {
            float* C = (float*)Cv + (size_t)bz * sC;
            float* C0 = C + (size_t)r0 * N + col;
            float* C1 = C + (size_t)(r0 + 8) * N + col;
            const float bv0 = bias ? bias[r0] : 0.f;
            const float bv1 = bias ? bias[r0 + 8] : 0.f;
            const float* R0 = resid ? resid + (size_t)bz * sR + (size_t)r0 * N + col : (const float*)0;
            const float* R1 = resid ? resid + (size_t)bz * sR + (size_t)(r0 + 8) * N + col : (const float*)0;
            #pragma unroll
            for (int j = 0; j < 8; j++) {
                float2 v0 = make_float2(acc[mi][j][0] * alpha + bv0,
                                        acc[mi][j][1] * alpha + bv0);
                float2 v1 = make_float2(acc[mi][j][2] * alpha + bv1,
                                        acc[mi][j][3] * alpha + bv1);
                if (resid) {
                    float2 q0 = *(const float2*)(R0 + j * 8);
                    float2 q1 = *(const float2*)(R1 + j * 8);
                    v0.x += q0.x; v0.y += q0.y;
                    v1.x += q1.x; v1.y += q1.y;
                }
                *(float2*)(C0 + j * 8) = v0;
                *(float2*)(C1 + j * 8) = v1;
            }
        }
    }
}

// ---------------------------------------------------------------------------
// rowinv: 1 / sum of 32 partials per row (deterministic fixed-order sum)
// ---------------------------------------------------------------------------
__global__ __launch_bounds__(256) void rowinv_kernel(
    const float* __restrict__ psum, float* __restrict__ rinv)
{
    const int idx = blockIdx.x * 256 + threadIdx.x;   // 0 .. B4*HW-1
    const float4* p = (const float4*)(psum + (size_t)idx * 32);
    float s = 0.f;
    #pragma unroll
    for (int i = 0; i < 8; i++) {
        float4 v = p[i];
        s += v.x + v.y + v.z + v.w;
    }
    rinv[idx] = 1.f / s;
}

// ---------------------------------------------------------------------------
// Launcher
// ---------------------------------------------------------------------------
extern "C" void kernel_launch(void* const* d_in, const int* in_sizes, int n_in,
                              void* d_out, int out_size)
{
    (void)in_sizes; (void)n_in; (void)out_size;
    const float* x    = (const float*)d_in[0];
    const float* gn_w = (const float*)d_in[1];
    const float* gn_b = (const float*)d_in[2];
    const float* wq   = (const float*)d_in[3];
    const float* bq   = (const float*)d_in[4];
    const float* wk   = (const float*)d_in[5];
    const float* bk   = (const float*)d_in[6];
    const float* wv   = (const float*)d_in[7];
    const float* bv   = (const float*)d_in[8];
    const float* wo   = (const float*)d_in[9];
    const float* bo   = (const float*)d_in[10];
    float* out = (float*)d_out;

    bf16 *h_, *qkv, *o, *p, *w;
    float *bqkv, *ps, *ri;
    cudaGetSymbolAddress((void**)&h_,  g_h);
    cudaGetSymbolAddress((void**)&qkv, g_qkv);
    cudaGetSymbolAddress((void**)&o,   g_o);
    cudaGetSymbolAddress((void**)&p,   g_p);
    cudaGetSymbolAddress((void**)&w,   g_w);
    cudaGetSymbolAddress((void**)&bqkv, g_bqkv);
    cudaGetSymbolAddress((void**)&ps,  g_ps);
    cudaGetSymbolAddress((void**)&ri,  g_ri);

    const int SMEM = 49152;
    cudaFuncSetAttribute(bfgemm<0, 0, 1, 0>, cudaFuncAttributeMaxDynamicSharedMemorySize, SMEM);
    cudaFuncSetAttribute(bfgemm<1, 0, 1, 1>, cudaFuncAttributeMaxDynamicSharedMemorySize, SMEM);
    cudaFuncSetAttribute(bfgemm<0, 1, 1, 2>, cudaFuncAttributeMaxDynamicSharedMemorySize, SMEM);
    cudaFuncSetAttribute(bfgemm<0, 0, 0, 0>, cudaFuncAttributeMaxDynamicSharedMemorySize, SMEM);

    const long long SC  = (long long)C512 * HW;   // one [c][s] plane
    const long long SC3 = 3 * SC;                 // qkv batch stride
    const long long SS  = (long long)HW * HW;
    const int WSZ = C512 * C512;
    const float scale = 0.044194173824159216f;    // 512^-0.5

    convw_kernel<<<4096, 256>>>(wq, wk, wv, wo, w);
    convb_kernel<<<6, 256>>>(bq, bk, bv, bqkv);
    groupnorm_kernel<<<B4 * NG, 256>>>(x, gn_w, gn_b, h_);

    // Fused QKV: qkv[m][s] = sum_c Wqkv[m][c] * h[c][s] + bqkv[m], m in [0,1536)
    dim3 gQKV(HW / 128, 1536 / 128, B4);          // (32, 12, 4)
    bfgemm<0, 0, 1, 0><<<gQKV, 256, SMEM>>>(1536, HW, C512,
        w, 0, h_, SC, qkv, SC3, bqkv, nullptr, 0, nullptr, nullptr, 1.f);

    // p[i][j] = exp(scale * sum_c q[c][i] k[c][j]); partial row sums -> ps
    dim3 gS(HW / 128, HW / 128, B4);              // (32, 32, 4)
    bfgemm<1, 0, 1, 1><<<gS, 256, SMEM>>>(HW, HW, C512,
        qkv, SC3, qkv + SC, SC3, p, SS, nullptr, nullptr, 0, ps, nullptr, scale);

    rowinv_kernel<<<B4 * HW / 256, 256>>>(ps, ri);

    // o[c][i] = (sum_j v[c][j] * p[i][j]) * rinv[i]
    dim3 gO(HW / 128, C512 / 128, B4);            // (32, 4, 4)
    bfgemm<0, 1, 1, 2><<<gO, 256, SMEM>>>(C512, HW, HW,
        qkv + 2 * SC, SC3, p, SS, o, SC, nullptr, nullptr, 0, nullptr, ri, 1.f);

    // out[m][s] = sum_c Wo[m][c] * o[c][s] + bo[m] + x[m][s]
    bfgemm<0, 0, 0, 0><<<gO, 256, SMEM>>>(C512, HW, C512,
        w + 3 * WSZ, 0, o, SC, out, SC, bo, x, SC, nullptr, nullptr, 1.f);
}

// round 12
// speedup vs baseline: 6.7280x; 1.0906x over previous
#include <cuda_runtime.h>
#include <cuda_bf16.h>
#include <math.h>
#include <stdint.h>

#define B4 4
#define C512 512
#define HW 4096
#define NG 32
typedef __nv_bfloat16 bf16;

// ---------------------------------------------------------------------------
// Scratch (device globals — no runtime allocation allowed)
// g_qkv: [b][1536][s]  rows 0..511=q, 512..1023=k, 1024..1535=v  (bf16)
// ---------------------------------------------------------------------------
__device__ bf16 g_h  [(size_t)B4 * C512 * HW];
__device__ bf16 g_qkv[(size_t)B4 * 3 * C512 * HW];
__device__ bf16 g_o  [(size_t)B4 * C512 * HW];
__device__ bf16 g_p  [(size_t)B4 * HW * HW];            // e = exp(scores) bf16
__device__ bf16 g_w  [4 * C512 * C512];
__device__ float g_bqkv[3 * C512];
__device__ float g_ps[(size_t)B4 * HW * 32];            // per-(row, jtile) partials
__device__ float g_ri[(size_t)B4 * HW];                 // 1/rowsum

// ---------------------------------------------------------------------------
// Helpers
// ---------------------------------------------------------------------------
__device__ __forceinline__ uint32_t packbf(float e0, float e1) {
    uint32_t r;
    asm("cvt.rn.bf16x2.f32 %0, %1, %2;" : "=r"(r) : "f"(e1), "f"(e0));
    return r;
}
__device__ __forceinline__ uint32_t cvta_s(const void* p) {
    return (uint32_t)__cvta_generic_to_shared(p);
}
__device__ __forceinline__ void ldsm4(uint32_t* r, uint32_t a) {
    asm volatile("ldmatrix.sync.aligned.m8n8.x4.shared.b16 {%0,%1,%2,%3}, [%4];"
                 : "=r"(r[0]), "=r"(r[1]), "=r"(r[2]), "=r"(r[3]) : "r"(a));
}
__device__ __forceinline__ void ldsm4t(uint32_t* r, uint32_t a) {
    asm volatile("ldmatrix.sync.aligned.m8n8.x4.trans.shared.b16 {%0,%1,%2,%3}, [%4];"
                 : "=r"(r[0]), "=r"(r[1]), "=r"(r[2]), "=r"(r[3]) : "r"(a));
}
__device__ __forceinline__ void cpasync16(uint32_t dst, const void* src) {
    asm volatile("cp.async.cg.shared.global [%0], [%1], 16;" :: "r"(dst), "l"(src));
}
__device__ __forceinline__ void mma_bf16(float* c, const uint32_t* a, const uint32_t* b) {
    asm volatile(
        "mma.sync.aligned.m16n8k16.row.col.f32.bf16.bf16.f32 "
        "{%0,%1,%2,%3}, {%4,%5,%6,%7}, {%8,%9}, {%0,%1,%2,%3};"
        : "+f"(c[0]), "+f"(c[1]), "+f"(c[2]), "+f"(c[3])
        : "r"(a[0]), "r"(a[1]), "r"(a[2]), "r"(a[3]), "r"(b[0]), "r"(b[1]));
}

// ---------------------------------------------------------------------------
// Weight fp32 -> bf16 ; bias concat
// ---------------------------------------------------------------------------
__global__ __launch_bounds__(256) void convw_kernel(
    const float* __restrict__ w0, const float* __restrict__ w1,
    const float* __restrict__ w2, const float* __restrict__ w3,
    bf16* __restrict__ out)
{
    int i = blockIdx.x * 256 + threadIdx.x;
    const float* src = (i < 262144) ? w0 : (i < 524288) ? w1
                      : (i < 786432) ? w2 : w3;
    out[i] = __float2bfloat16(src[i & 262143]);
}
__global__ __launch_bounds__(256) void convb_kernel(
    const float* __restrict__ b0, const float* __restrict__ b1,
    const float* __restrict__ b2, float* __restrict__ out)
{
    int i = blockIdx.x * 256 + threadIdx.x;
    out[i] = (i < 512) ? b0[i] : (i < 1024) ? b1[i - 512] : b2[i - 1024];
}

// ---------------------------------------------------------------------------
// GroupNorm -> bf16 [b][c][s]
// ---------------------------------------------------------------------------
__global__ __launch_bounds__(256) void groupnorm_kernel(
    const float* __restrict__ x, const float* __restrict__ gamma,
    const float* __restrict__ beta, bf16* __restrict__ out)
{
    const int GSZ = (C512 / NG) * HW;
    int b = blockIdx.x >> 5;
    int g = blockIdx.x & 31;
    const float* xp = x + ((size_t)b * C512 + g * (C512 / NG)) * HW;
    bf16* op = out + ((size_t)b * C512 + g * (C512 / NG)) * HW;

    float s = 0.f, sq = 0.f;
    for (int i = threadIdx.x * 4; i < GSZ; i += blockDim.x * 4) {
        float4 v = *(const float4*)(xp + i);
        s  += v.x + v.y + v.z + v.w;
        sq += v.x * v.x + v.y * v.y + v.z * v.z + v.w * v.w;
    }
    __shared__ float red0[8], red1[8];
    #pragma unroll
    for (int o = 16; o > 0; o >>= 1) {
        s  += __shfl_xor_sync(0xffffffffu, s, o);
        sq += __shfl_xor_sync(0xffffffffu, sq, o);
    }
    if ((threadIdx.x & 31) == 0) { red0[threadIdx.x >> 5] = s; red1[threadIdx.x >> 5] = sq; }
    __syncthreads();
    s = 0.f; sq = 0.f;
    #pragma unroll
    for (int i = 0; i < 8; i++) { s += red0[i]; sq += red1[i]; }
    float mean = s / GSZ;
    float var  = sq / GSZ - mean * mean;
    float rstd = rsqrtf(var + 1e-6f);

    for (int i = threadIdx.x * 4; i < GSZ; i += blockDim.x * 4) {
        int c = g * (C512 / NG) + (i >> 12);
        float w  = gamma[c] * rstd;
        float bb = beta[c] - mean * w;
        float4 v = *(const float4*)(xp + i);
        uint2 pk;
        pk.x = packbf(v.x * w + bb, v.y * w + bb);
        pk.y = packbf(v.z * w + bb, v.w * w + bb);
        *(uint2*)(op + i) = pk;
    }
}

// ---------------------------------------------------------------------------
// bf16 HMMA GEMM: 128 threads, 4 warps (2x2), warp tile 64x64, BK=32,
// 3-stage cp.async, register fragment double-buffering.
// C[m][n] = alpha * sum_k A(m,k)*B(k,n)
// TA=0: A row-major MxK. TA=1: A stored KxM [ldmatrix.trans]
// TB=1: B stored NxK.    TB=0: B row-major KxN [trans]
// EPI: 0 normal (bias[m], optional fp32 resid)
//      1 p=bf16(exp(alpha*acc)) + per-(row,jtile) partial sums
//      2 multiply by nsc[n-col], bf16 out
// ---------------------------------------------------------------------------
template <int TA, int TB, int OUTBF, int EPI>
__global__ __launch_bounds__(128, 2) void bfgemm(
    int M, int N, int K,
    const bf16* __restrict__ A, long long sA,
    const bf16* __restrict__ B, long long sB,
    void* __restrict__ Cv, long long sC,
    const float* __restrict__ bias,
    const float* __restrict__ resid, long long sR,
    float* __restrict__ psum,
    const float* __restrict__ nsc,
    float alpha)
{
    extern __shared__ bf16 smbuf[];     // 3 stages x (A 4096 + B 4096)
    bf16* Ash = smbuf;
    bf16* Bsh = smbuf + 3 * 4096;

    const int tid = threadIdx.x, lane = tid & 31, wid = tid >> 5;
    const int bm0 = blockIdx.y * 128, bn0 = blockIdx.x * 128;
    const int bz = blockIdx.z;
    A += (size_t)bz * sA;
    B += (size_t)bz * sB;

    const int lda = TA ? M : K;
    const int ldb = TB ? K : N;
    const long long stepA = TA ? (long long)32 * lda : 32;
    const long long stepB = TB ? 32 : (long long)32 * ldb;

    const uint32_t As_u = cvta_s(Ash);
    const uint32_t Bs_u = cvta_s(Bsh);

    // cp.async: 4 x 16B chunks per operand per thread (128 thr x 4 = 512 chunks)
    uint32_t aOfs[4], aDst[4], bOfs[4], bDst[4];
    #pragma unroll
    for (int i = 0; i < 4; i++) {
        const int g = tid + i * 128;
        if (TA == 0) {
            int r = g >> 2, c = g & 3;
            aOfs[i] = (uint32_t)(r * lda + c * 8);
            aDst[i] = (uint32_t)(r * 4 + (c ^ ((r >> 1) & 3))) * 16;
        } else {
            int k = g >> 4, c = g & 15;
            aOfs[i] = (uint32_t)(k * lda + c * 8);
            aDst[i] = (uint32_t)(k * 16 + (c ^ (k & 7))) * 16;
        }
        if (TB == 1) {
            int r = g >> 2, c = g & 3;
            bOfs[i] = (uint32_t)(r * ldb + c * 8);
            bDst[i] = (uint32_t)(r * 4 + (c ^ ((r >> 1) & 3))) * 16;
        } else {
            int k = g >> 4, c = g & 15;
            bOfs[i] = (uint32_t)(k * ldb + c * 8);
            bDst[i] = (uint32_t)(k * 16 + (c ^ (k & 7))) * 16;
        }
    }
    const bf16* Abase = A + (TA == 0 ? (size_t)bm0 * lda : (size_t)bm0);
    const bf16* Bbase = B + (TB == 1 ? (size_t)bn0 * ldb : (size_t)bn0);

    // ldmatrix fragment byte offsets — fully precomputed per ks (swizzle applied
    // to the true chunk index; no post-swizzle flat offsets for row-major!)
    const int quad = lane >> 3, lrow = lane & 7;
    const int wm0 = (wid & 1) * 64, wn0 = (wid >> 1) * 64;
    uint32_t fA[2][4], fB[2][4];
    #pragma unroll
    for (int ks = 0; ks < 2; ks++) {
        #pragma unroll
        for (int mi = 0; mi < 4; mi++) {
            if (TA == 0) {
                int r = wm0 + mi * 16 + (quad & 1) * 8 + lrow;
                int c = 2 * ks + (quad >> 1);
                fA[ks][mi] = (uint32_t)(r * 4 + (c ^ ((r >> 1) & 3))) * 16;
            } else {
                int k = ks * 16 + (quad >> 1) * 8 + lrow;
                int c = ((wm0 + mi * 16) >> 3) + (quad & 1);
                fA[ks][mi] = (uint32_t)(k * 16 + (c ^ (k & 7))) * 16;
            }
        }
        #pragma unroll
        for (int nj = 0; nj < 4; nj++) {
            if (TB == 1) {
                int r = wn0 + nj * 16 + (quad & 1) * 8 + lrow;
                int c = 2 * ks + (quad >> 1);
                fB[ks][nj] = (uint32_t)(r * 4 + (c ^ ((r >> 1) & 3))) * 16;
            } else {
                int k = ks * 16 + (quad >> 1) * 8 + lrow;
                int c = ((wn0 + nj * 16) >> 3) + (quad & 1);
                fB[ks][nj] = (uint32_t)(k * 16 + (c ^ (k & 7))) * 16;
            }
        }
    }

    auto issue = [&](int st, int kt) {
        const bf16* ag = Abase + (size_t)kt * stepA;
        const bf16* bg = Bbase + (size_t)kt * stepB;
        #pragma unroll
        for (int i = 0; i < 4; i++) {
            cpasync16(As_u + st * 8192 + aDst[i], ag + aOfs[i]);
            cpasync16(Bs_u + st * 8192 + bDst[i], bg + bOfs[i]);
        }
    };

    uint32_t aFr[2][4][4], bFr[2][4][4];
    auto loadfrag = [&](int set, int st, int ks) {
        const uint32_t ab = As_u + st * 8192;
        const uint32_t bb = Bs_u + st * 8192;
        #pragma unroll
        for (int mi = 0; mi < 4; mi++) {
            if (TA == 0) ldsm4(aFr[set][mi], ab + fA[ks][mi]);
            else         ldsm4t(aFr[set][mi], ab + fA[ks][mi]);
        }
        #pragma unroll
        for (int nj = 0; nj < 4; nj++) {
            if (TB == 1) ldsm4(bFr[set][nj], bb + fB[ks][nj]);
            else         ldsm4t(bFr[set][nj], bb + fB[ks][nj]);
        }
    };

    float acc[4][8][4] = {};
    auto domma = [&](int set) {
        #pragma unroll
        for (int mi = 0; mi < 4; mi++)
            #pragma unroll
            for (int nj = 0; nj < 4; nj++) {
                uint32_t bl[2] = {bFr[set][nj][0], bFr[set][nj][2]};
                uint32_t bh[2] = {bFr[set][nj][1], bFr[set][nj][3]};
                mma_bf16(acc[mi][nj * 2 + 0], aFr[set][mi], bl);
                mma_bf16(acc[mi][nj * 2 + 1], aFr[set][mi], bh);
            }
    };

    const int nk = K / 32;
    issue(0, 0); asm volatile("cp.async.commit_group;" ::: "memory");
    issue(1, 1); asm volatile("cp.async.commit_group;" ::: "memory");
    asm volatile("cp.async.wait_group 1;" ::: "memory");
    __syncthreads();
    loadfrag(0, 0, 0);

    for (int kt = 0; kt < nk; kt++) {
        const int st = kt % 3;
        // ks = 0: prefetch ks=1 frags, issue tile kt+2, mma set0
        loadfrag(1, st, 1);
        if (kt + 2 < nk) issue((kt + 2) % 3, kt + 2);
        asm volatile("cp.async.commit_group;" ::: "memory");
        domma(0);
        // ks = 1: wait tile kt+1, prefetch its ks=0 frags, mma set1
        asm volatile("cp.async.wait_group 1;" ::: "memory");
        __syncthreads();
        if (kt + 1 < nk) loadfrag(0, (kt + 1) % 3, 0);
        domma(1);
    }

    // ---------------- epilogue ----------------
    const int lr = lane >> 2, lc = lane & 3;

    if (EPI == 1) {
        __syncthreads();
        float* ps = (float*)smbuf;             // [128][2]
        bf16* C = (bf16*)Cv + (size_t)bz * sC;
        #pragma unroll
        for (int mi = 0; mi < 4; mi++) {
            const int r0 = bm0 + wm0 + mi * 16 + lr;
            const int col = bn0 + wn0 + 2 * lc;
            uint32_t* C0 = (uint32_t*)(C + (size_t)r0 * N + col);
            uint32_t* C1 = (uint32_t*)(C + (size_t)(r0 + 8) * N + col);
            float s0 = 0.f, s1 = 0.f;
            #pragma unroll
            for (int j = 0; j < 8; j++) {
                float e00 = __expf(acc[mi][j][0] * alpha);
                float e01 = __expf(acc[mi][j][1] * alpha);
                float e10 = __expf(acc[mi][j][2] * alpha);
                float e11 = __expf(acc[mi][j][3] * alpha);
                C0[j * 4] = packbf(e00, e01);
                C1[j * 4] = packbf(e10, e11);
                s0 += e00 + e01;
                s1 += e10 + e11;
            }
            float v0 = s0, v1 = s1;
            v0 += __shfl_xor_sync(0xffffffffu, v0, 1);
            v0 += __shfl_xor_sync(0xffffffffu, v0, 2);
            v1 += __shfl_xor_sync(0xffffffffu, v1, 1);
            v1 += __shfl_xor_sync(0xffffffffu, v1, 2);
            if (lc == 0) {
                ps[(wm0 + mi * 16 + lr) * 2 + (wn0 >> 6)] = v0;
                ps[(wm0 + mi * 16 + 8 + lr) * 2 + (wn0 >> 6)] = v1;
            }
        }
        __syncthreads();
        float t = ps[tid * 2 + 0] + ps[tid * 2 + 1];
        psum[((size_t)bz * HW + bm0 + tid) * 32 + blockIdx.x] = t;
        return;
    }

    #pragma unroll
    for (int mi = 0; mi < 4; mi++) {
        const int r0 = bm0 + wm0 + mi * 16 + lr;
        const int col = bn0 + wn0 + 2 * lc;
        if (OUTBF) {
            bf16* C = (bf16*)Cv + (size_t)bz * sC;
            uint32_t* C0 = (uint32_t*)(C + (size_t)r0 * N + col);
            uint32_t* C1 = (uint32_t*)(C + (size_t)(r0 + 8) * N + col);
            const float bv0 = (EPI == 0 && bias) ? bias[r0] : 0.f;
            const float bv1 = (EPI == 0 && bias) ? bias[r0 + 8] : 0.f;
            #pragma unroll
            for (int j = 0; j < 8; j++) {
                float f0 = 1.f, f1 = 1.f;
                if (EPI == 2) {
                    float2 ff = *(const float2*)(nsc + (size_t)bz * HW + col + j * 8);
                    f0 = ff.x; f1 = ff.y;
                }
                C0[j * 4] = packbf(acc[mi][j][0] * alpha * f0 + bv0,
                                   acc[mi][j][1] * alpha * f1 + bv0);
                C1[j * 4] = packbf(acc[mi][j][2] * alpha * f0 + bv1,
                                   acc[mi][j][3] * alpha * f1 + bv1);
            }
        } else {
            float* C = (float*)Cv + (size_t)bz * sC;
            float* C0 = C + (size_t)r0 * N + col;
            float* C1 = C + (size_t)(r0 + 8) * N + col;
            const float bv0 = bias ? bias[r0] : 0.f;
            const float bv1 = bias ? bias[r0 + 8] : 0.f;
            const float* R0 = resid ? resid + (size_t)bz * sR + (size_t)r0 * N + col : (const float*)0;
            const float* R1 = resid ? resid + (size_t)bz * sR + (size_t)(r0 + 8) * N + col : (const float*)0;
            #pragma unroll
            for (int j = 0; j < 8; j++) {
                float2 v0 = make_float2(acc[mi][j][0] * alpha + bv0,
                                        acc[mi][j][1] * alpha + bv0);
                float2 v1 = make_float2(acc[mi][j][2] * alpha + bv1,
                                        acc[mi][j][3] * alpha + bv1);
                if (resid) {
                    float2 q0 = *(const float2*)(R0 + j * 8);
                    float2 q1 = *(const float2*)(R1 + j * 8);
                    v0.x += q0.x; v0.y += q0.y;
                    v1.x += q1.x; v1.y += q1.y;
                }
                *(float2*)(C0 + j * 8) = v0;
                *(float2*)(C1 + j * 8) = v1;
            }
        }
    }
}

// ---------------------------------------------------------------------------
// rowinv: 1 / sum of 32 partials per row
// ---------------------------------------------------------------------------
__global__ __launch_bounds__(256) void rowinv_kernel(
    const float* __restrict__ psum, float* __restrict__ rinv)
{
    const int idx = blockIdx.x * 256 + threadIdx.x;
    const float4* p = (const float4*)(psum + (size_t)idx * 32);
    float s = 0.f;
    #pragma unroll
    for (int i = 0; i < 8; i++) {
        float4 v = p[i];
        s += v.x + v.y + v.z + v.w;
    }
    rinv[idx] = 1.f / s;
}

// ---------------------------------------------------------------------------
// Launcher
// ---------------------------------------------------------------------------
extern "C" void kernel_launch(void* const* d_in, const int* in_sizes, int n_in,
                              void* d_out, int out_size)
{
    (void)in_sizes; (void)n_in; (void)out_size;
    const float* x    = (const float*)d_in[0];
    const float* gn_w = (const float*)d_in[1];
    const float* gn_b = (const float*)d_in[2];
    const float* wq   = (const float*)d_in[3];
    const float* bq   = (const float*)d_in[4];
    const float* wk   = (const float*)d_in[5];
    const float* bk   = (const float*)d_in[6];
    const float* wv   = (const float*)d_in[7];
    const float* bv   = (const float*)d_in[8];
    const float* wo   = (const float*)d_in[9];
    const float* bo   = (const float*)d_in[10];
    float* out = (float*)d_out;

    bf16 *h_, *qkv, *o, *p, *w;
    float *bqkv, *ps, *ri;
    cudaGetSymbolAddress((void**)&h_,  g_h);
    cudaGetSymbolAddress((void**)&qkv, g_qkv);
    cudaGetSymbolAddress((void**)&o,   g_o);
    cudaGetSymbolAddress((void**)&p,   g_p);
    cudaGetSymbolAddress((void**)&w,   g_w);
    cudaGetSymbolAddress((void**)&bqkv, g_bqkv);
    cudaGetSymbolAddress((void**)&ps,  g_ps);
    cudaGetSymbolAddress((void**)&ri,  g_ri);

    const int SMEM = 49152;
    cudaFuncSetAttribute(bfgemm<0, 0, 1, 0>, cudaFuncAttributeMaxDynamicSharedMemorySize, SMEM);
    cudaFuncSetAttribute(bfgemm<1, 0, 1, 1>, cudaFuncAttributeMaxDynamicSharedMemorySize, SMEM);
    cudaFuncSetAttribute(bfgemm<0, 1, 1, 2>, cudaFuncAttributeMaxDynamicSharedMemorySize, SMEM);
    cudaFuncSetAttribute(bfgemm<0, 0, 0, 0>, cudaFuncAttributeMaxDynamicSharedMemorySize, SMEM);

    const long long SC  = (long long)C512 * HW;
    const long long SC3 = 3 * SC;
    const long long SS  = (long long)HW * HW;
    const int WSZ = C512 * C512;
    const float scale = 0.044194173824159216f;    // 512^-0.5

    convw_kernel<<<4096, 256>>>(wq, wk, wv, wo, w);
    convb_kernel<<<6, 256>>>(bq, bk, bv, bqkv);
    groupnorm_kernel<<<B4 * NG, 256>>>(x, gn_w, gn_b, h_);

    // Fused QKV: qkv[m][s] = sum_c Wqkv[m][c] * h[c][s] + bqkv[m]
    dim3 gQKV(HW / 128, 1536 / 128, B4);
    bfgemm<0, 0, 1, 0><<<gQKV, 128, SMEM>>>(1536, HW, C512,
        w, 0, h_, SC, qkv, SC3, bqkv, nullptr, 0, nullptr, nullptr, 1.f);

    // p[i][j] = exp(scale * sum_c q[c][i] k[c][j]); partial row sums
    dim3 gS(HW / 128, HW / 128, B4);
    bfgemm<1, 0, 1, 1><<<gS, 128, SMEM>>>(HW, HW, C512,
        qkv, SC3, qkv + SC, SC3, p, SS, nullptr, nullptr, 0, ps, nullptr, scale);

    rowinv_kernel<<<B4 * HW / 256, 256>>>(ps, ri);

    // o[c][i] = (sum_j v[c][j] * p[i][j]) * rinv[i]
    dim3 gO(HW / 128, C512 / 128, B4);
    bfgemm<0, 1, 1, 2><<<gO, 128, SMEM>>>(C512, HW, HW,
        qkv + 2 * SC, SC3, p, SS, o, SC, nullptr, nullptr, 0, nullptr, ri, 1.f);

    // out[m][s] = sum_c Wo[m][c] * o[c][s] + bo[m] + x[m][s]
    bfgemm<0, 0, 0, 0><<<gO, 128, SMEM>>>(C512, HW, C512,
        w + 3 * WSZ, 0, o, SC, out, SC, bo, x, SC, nullptr, nullptr, 1.f);
}